// round 14
// baseline (speedup 1.0000x reference)
#include <cuda_runtime.h>
#include <cuda_bf16.h>
#include <cstdint>
#include <cstddef>

#define Bsz 2
#define Ssz 1024
#define Dm  1024
#define Hh  16
#define DKk 64
#define Ff  4096
#define Vv  32000
#define Ll  8
#define TOK (Bsz*Ssz)
#define BH  (Bsz*Hh)

// ===================== scratch ==============================================
__device__ float g_x [TOK*Dm];
__device__ __nv_bfloat16 g_hh[TOK*Dm],  g_hl[TOK*Dm];
__device__ __nv_bfloat16 g_oh[TOK*Dm],  g_ol[TOK*Dm];
__device__ __nv_bfloat16 g_ffh[TOK*Ff], g_ffl[TOK*Ff];
__device__ __nv_bfloat16 g_qh[TOK*Dm], g_ql[TOK*Dm];   // [B,H,S,64]
__device__ __nv_bfloat16 g_kh[TOK*Dm], g_kl[TOK*Dm];   // [B,H,S,64]
__device__ __nv_bfloat16 g_vh[TOK*Dm], g_vl[TOK*Dm];   // [B,H,64,S]  (transposed!)

#define SQW ((size_t)2*Dm*Dm)
#define SW1 ((size_t)2*Dm*Ff)
#define OFF_Q  ((size_t)0)
#define OFF_K  (OFF_Q  + (size_t)Ll*SQW)
#define OFF_V  (OFF_K  + (size_t)Ll*SQW)
#define OFF_O  (OFF_V  + (size_t)Ll*SQW)
#define OFF_W1 (OFF_O  + (size_t)Ll*SQW)
#define OFF_W2 (OFF_W1 + (size_t)Ll*SW1)
#define OFF_WO (OFF_W2 + (size_t)Ll*SW1)
#define WC_TOTAL (OFF_WO + (size_t)2*Dm*Vv)
__device__ __nv_bfloat16 g_wc[WC_TOTAL];

__device__ __forceinline__ void split_bf16(float v, __nv_bfloat16& h, __nv_bfloat16& l) {
    h = __float2bfloat16(v);
    l = __float2bfloat16(v - __bfloat162float(h));
}
__device__ __forceinline__ uint32_t pack2(__nv_bfloat16 a, __nv_bfloat16 b) {
    return (uint32_t)__bfloat16_as_ushort(a) | ((uint32_t)__bfloat16_as_ushort(b) << 16);
}
__device__ __forceinline__ void cpa16(void* s, const void* g) {
    uint32_t sa = (uint32_t)__cvta_generic_to_shared(s);
    asm volatile("cp.async.cg.shared.global [%0], [%1], 16;" :: "r"(sa), "l"(g));
}
#define CP_COMMIT() asm volatile("cp.async.commit_group;" ::: "memory")
#define CP_WAIT1()  asm volatile("cp.async.wait_group 1;" ::: "memory")
#define CP_WAIT0()  asm volatile("cp.async.wait_group 0;" ::: "memory")

__device__ __forceinline__ void ldsm4(uint32_t addr, uint32_t* r) {
    asm volatile("ldmatrix.sync.aligned.m8n8.x4.shared.b16 {%0,%1,%2,%3}, [%4];"
        : "=r"(r[0]), "=r"(r[1]), "=r"(r[2]), "=r"(r[3]) : "r"(addr));
}
__device__ __forceinline__ void mma16816(float* d, const uint32_t* a, const uint32_t* b) {
    asm volatile("mma.sync.aligned.m16n8k16.row.col.f32.bf16.bf16.f32 "
        "{%0,%1,%2,%3}, {%4,%5,%6,%7}, {%8,%9}, {%0,%1,%2,%3};"
        : "+f"(d[0]), "+f"(d[1]), "+f"(d[2]), "+f"(d[3])
        : "r"(a[0]), "r"(a[1]), "r"(a[2]), "r"(a[3]), "r"(b[0]), "r"(b[1]));
}

// ======= weight convert: W [K,N] fp32 -> hi/lo [N,K] bf16 (transpose) =======
__global__ __launch_bounds__(256) void convert_w_k(
    const float* __restrict__ W, __nv_bfloat16* __restrict__ out, int Kd, int Nd)
{
    __shared__ float t[32][33];
    const int l = blockIdx.z;
    const float* Wl = W + (size_t)l * Kd * Nd;
    __nv_bfloat16* hi = out + (size_t)l * 2 * Kd * Nd;
    __nv_bfloat16* lo = hi + (size_t)Kd * Nd;
    const int nb = blockIdx.x * 32, kb = blockIdx.y * 32;
    const int tx = threadIdx.x & 31, ty = threadIdx.x >> 5;
    #pragma unroll
    for (int j = 0; j < 32; j += 8)
        t[ty + j][tx] = Wl[(size_t)(kb + ty + j) * Nd + nb + tx];
    __syncthreads();
    #pragma unroll
    for (int j = 0; j < 32; j += 8) {
        const int n = nb + ty + j, k = kb + tx;
        float v = t[tx][ty + j];
        __nv_bfloat16 h, l2; split_bf16(v, h, l2);
        hi[(size_t)n * Kd + k] = h;
        lo[(size_t)n * Kd + k] = l2;
    }
}

// ===================== GEMM flags / args ====================================
#define F_BIAS 1
#define F_RES  2
#define F_RELU 4
#define F_QKVOUT 8
#define F_SPLITOUT 16

struct GemmArgs {
    const __nv_bfloat16 *Ahi, *Alo;
    const __nv_bfloat16 *Bhi[3], *Blo[3];
    const float* bias[3];
    const float* Res;
    float* C[3];
    __nv_bfloat16 *Chi[3], *Clo[3];
    int K;
    int ldc;
};

// ===================== GEMM v4: BM=128 ======================================
#define PITB 80
#define AH_OFF 0
#define AL_OFF (128*PITB)
#define BH_OFF (2*128*PITB)
#define BL_OFF (3*128*PITB)
#define STGB   (4*128*PITB)
#define SMEM_GM (3*STGB)               // 122880

template<int FLAGS>
__global__ __launch_bounds__(256) void mma_gemm_k(GemmArgs ga)
{
    constexpr int BM = 128, BN = 128, BK = 32;
    extern __shared__ __nv_bfloat16 smb[];
    char* smc = (char*)smb;

    const int tid = threadIdx.x, wid = tid >> 5, lane = tid & 31;
    const int z = blockIdx.z;
    const int Kd = ga.K;
    const __nv_bfloat16* Ah = ga.Ahi + (size_t)blockIdx.y * BM * Kd;
    const __nv_bfloat16* Al = ga.Alo + (size_t)blockIdx.y * BM * Kd;
    const __nv_bfloat16* Bh = ga.Bhi[z] + (size_t)blockIdx.x * BN * Kd;
    const __nv_bfloat16* Bl = ga.Blo[z] + (size_t)blockIdx.x * BN * Kd;
    const int wm = wid & 3, wn = wid >> 2;

    auto stage_load = [&](int buf, int k0) {
        char* s = smc + buf * STGB;
        #pragma unroll
        for (int ss = 0; ss < 2; ss++) {
            const int slot = tid + ss * 256;
            const int r = slot >> 2, c = slot & 3;
            cpa16(s + AH_OFF + r * PITB + c * 16, Ah + (size_t)r * Kd + k0 + c * 8);
            cpa16(s + AL_OFF + r * PITB + c * 16, Al + (size_t)r * Kd + k0 + c * 8);
        }
        #pragma unroll
        for (int ss = 0; ss < 2; ss++) {
            const int slot = tid + ss * 256;
            const int r = slot >> 2, c = slot & 3;
            cpa16(s + BH_OFF + r * PITB + c * 16, Bh + (size_t)r * Kd + k0 + c * 8);
            cpa16(s + BL_OFF + r * PITB + c * 16, Bl + (size_t)r * Kd + k0 + c * 8);
        }
        CP_COMMIT();
    };

    uint32_t offA[2];
    #pragma unroll
    for (int ii = 0; ii < 2; ii++)
        offA[ii] = (uint32_t)((wm * 32 + ii * 16 + (lane & 15)) * PITB + ((lane >> 4) & 1) * 16);
    uint32_t offB[4];
    #pragma unroll
    for (int jj = 0; jj < 4; jj++)
        offB[jj] = (uint32_t)((wn * 64 + jj * 16 + (lane & 7) + ((lane >> 4) & 1) * 8) * PITB
                              + ((lane >> 3) & 1) * 16);

    const uint32_t smem_u32 = (uint32_t)__cvta_generic_to_shared(smc);

    float acc[2][8][4];
    #pragma unroll
    for (int i = 0; i < 2; i++)
        #pragma unroll
        for (int j = 0; j < 8; j++)
            #pragma unroll
            for (int e = 0; e < 4; e++) acc[i][j][e] = 0.f;

    const int nst = Kd / BK;
    stage_load(0, 0);
    stage_load(1, BK);
    for (int i = 0; i < nst; i++) {
        if (i + 1 < nst) { CP_WAIT1(); } else { CP_WAIT0(); }
        __syncthreads();
        if (i + 2 < nst) stage_load((i + 2) % 3, (i + 2) * BK);
        const uint32_t sb = smem_u32 + (uint32_t)((i % 3) * STGB);
        #pragma unroll
        for (int kk = 0; kk < BK; kk += 16) {
            const uint32_t kb = sb + kk * 2;
            uint32_t ah[2][4], al[2][4], bh[16], bl[16];
            #pragma unroll
            for (int ii = 0; ii < 2; ii++) {
                ldsm4(kb + AH_OFF + offA[ii], ah[ii]);
                ldsm4(kb + AL_OFF + offA[ii], al[ii]);
            }
            #pragma unroll
            for (int jj = 0; jj < 4; jj++) {
                ldsm4(kb + BH_OFF + offB[jj], bh + jj * 4);
                ldsm4(kb + BL_OFF + offB[jj], bl + jj * 4);
            }
            #pragma unroll
            for (int ii = 0; ii < 2; ii++)
                #pragma unroll
                for (int j = 0; j < 8; j++) mma16816(acc[ii][j], ah[ii], bh + j * 2);
            #pragma unroll
            for (int ii = 0; ii < 2; ii++)
                #pragma unroll
                for (int j = 0; j < 8; j++) mma16816(acc[ii][j], ah[ii], bl + j * 2);
            #pragma unroll
            for (int ii = 0; ii < 2; ii++)
                #pragma unroll
                for (int j = 0; j < 8; j++) mma16816(acc[ii][j], al[ii], bh + j * 2);
        }
        __syncthreads();
    }

    constexpr int SP = BN + 4;
    float* st = (float*)smb;
    const int er = lane >> 2, ec = (lane & 3) * 2;
    #pragma unroll
    for (int ii = 0; ii < 2; ii++)
        #pragma unroll
        for (int j = 0; j < 8; j++) {
            const int r0 = wm * 32 + ii * 16 + er;
            const int c0 = wn * 64 + j * 8 + ec;
            st[r0 * SP + c0]       = acc[ii][j][0];
            st[r0 * SP + c0 + 1]   = acc[ii][j][1];
            st[(r0+8) * SP + c0]     = acc[ii][j][2];
            st[(r0+8) * SP + c0 + 1] = acc[ii][j][3];
        }
    __syncthreads();

    const float* bias = ga.bias[z] + (size_t)blockIdx.x * BN;
    #pragma unroll
    for (int jj = 0; jj < 16; jj++) {
        const int idx = tid + jj * 256;
        const int r = idx >> 5, c4 = (idx & 31) * 4;
        float4 v;
        v.x = st[r * SP + c4 + 0]; v.y = st[r * SP + c4 + 1];
        v.z = st[r * SP + c4 + 2]; v.w = st[r * SP + c4 + 3];
        if (FLAGS & F_BIAS) {
            float4 b4 = *(const float4*)(bias + c4);
            v.x += b4.x; v.y += b4.y; v.z += b4.z; v.w += b4.w;
        }
        if (FLAGS & F_RELU) {
            v.x = fmaxf(v.x, 0.f); v.y = fmaxf(v.y, 0.f);
            v.z = fmaxf(v.z, 0.f); v.w = fmaxf(v.w, 0.f);
        }
        if (FLAGS & F_SPLITOUT) {
            const size_t base = (size_t)(blockIdx.y * BM + r) * ga.ldc + blockIdx.x * BN + c4;
            __nv_bfloat16 h[4], l[4];
            split_bf16(v.x, h[0], l[0]); split_bf16(v.y, h[1], l[1]);
            split_bf16(v.z, h[2], l[2]); split_bf16(v.w, h[3], l[3]);
            *(uint2*)(ga.Chi[z] + base) = *(uint2*)h;
            *(uint2*)(ga.Clo[z] + base) = *(uint2*)l;
        } else {
            if (FLAGS & F_RES) {
                const float* R = ga.Res + (size_t)blockIdx.y * BM * ga.ldc + (size_t)blockIdx.x * BN;
                float4 r4 = *(const float4*)(R + (size_t)r * ga.ldc + c4);
                v.x += r4.x; v.y += r4.y; v.z += r4.z; v.w += r4.w;
            }
            float* C = ga.C[z] + (size_t)blockIdx.y * BM * ga.ldc + (size_t)blockIdx.x * BN;
            *(float4*)(C + (size_t)r * ga.ldc + c4) = v;
        }
    }
}

// ===================== GEMM v5: BM=256, warp tile 64x64 =====================
#define AH5_OFF 0
#define AL5_OFF (256*PITB)
#define BH5_OFF (2*256*PITB)
#define BL5_OFF (2*256*PITB + 128*PITB)
#define STGB5   (2*256*PITB + 2*128*PITB)
#define SMEM_GM5 (3*STGB5)                   // 184320

template<int FLAGS>
__global__ __launch_bounds__(256) void mma_gemm256_k(GemmArgs ga)
{
    constexpr int BM = 256, BN = 128, BK = 32;
    extern __shared__ __nv_bfloat16 smb[];
    char* smc = (char*)smb;

    const int tid = threadIdx.x, wid = tid >> 5, lane = tid & 31;
    const int z = blockIdx.z;
    const int Kd = ga.K;
    const __nv_bfloat16* Ah = ga.Ahi + (size_t)blockIdx.y * BM * Kd;
    const __nv_bfloat16* Al = ga.Alo + (size_t)blockIdx.y * BM * Kd;
    const __nv_bfloat16* Bh = ga.Bhi[z] + (size_t)blockIdx.x * BN * Kd;
    const __nv_bfloat16* Bl = ga.Blo[z] + (size_t)blockIdx.x * BN * Kd;
    const int wm = wid & 3, wn = wid >> 2;

    auto stage_load = [&](int buf, int k0) {
        char* s = smc + buf * STGB5;
        #pragma unroll
        for (int ss = 0; ss < 4; ss++) {
            const int slot = tid + ss * 256;
            const int r = slot >> 2, c = slot & 3;
            cpa16(s + AH5_OFF + r * PITB + c * 16, Ah + (size_t)r * Kd + k0 + c * 8);
            cpa16(s + AL5_OFF + r * PITB + c * 16, Al + (size_t)r * Kd + k0 + c * 8);
        }
        #pragma unroll
        for (int ss = 0; ss < 2; ss++) {
            const int slot = tid + ss * 256;
            const int r = slot >> 2, c = slot & 3;
            cpa16(s + BH5_OFF + r * PITB + c * 16, Bh + (size_t)r * Kd + k0 + c * 8);
            cpa16(s + BL5_OFF + r * PITB + c * 16, Bl + (size_t)r * Kd + k0 + c * 8);
        }
        CP_COMMIT();
    };

    uint32_t offA[4];
    #pragma unroll
    for (int mi = 0; mi < 4; mi++)
        offA[mi] = (uint32_t)((wm * 64 + mi * 16 + (lane & 15)) * PITB + ((lane >> 4) & 1) * 16);
    uint32_t offB[4];
    #pragma unroll
    for (int nj = 0; nj < 4; nj++)
        offB[nj] = (uint32_t)((wn * 64 + nj * 16 + (lane & 7) + ((lane >> 4) & 1) * 8) * PITB
                              + ((lane >> 3) & 1) * 16);

    const uint32_t smem_u32 = (uint32_t)__cvta_generic_to_shared(smc);

    float acc[4][8][4];
    #pragma unroll
    for (int i = 0; i < 4; i++)
        #pragma unroll
        for (int j = 0; j < 8; j++)
            #pragma unroll
            for (int e = 0; e < 4; e++) acc[i][j][e] = 0.f;

    const int nst = Kd / BK;
    stage_load(0, 0);
    stage_load(1, BK);
    for (int i = 0; i < nst; i++) {
        if (i + 1 < nst) { CP_WAIT1(); } else { CP_WAIT0(); }
        __syncthreads();
        if (i + 2 < nst) stage_load((i + 2) % 3, (i + 2) * BK);
        const uint32_t sb = smem_u32 + (uint32_t)((i % 3) * STGB5);
        #pragma unroll
        for (int kk = 0; kk < BK; kk += 16) {
            const uint32_t kb = sb + kk * 2;
            uint32_t ah[4][4], al[4][4], bb[16];
            #pragma unroll
            for (int mi = 0; mi < 4; mi++) {
                ldsm4(kb + AH5_OFF + offA[mi], ah[mi]);
                ldsm4(kb + AL5_OFF + offA[mi], al[mi]);
            }
            #pragma unroll
            for (int nj = 0; nj < 4; nj++) ldsm4(kb + BH5_OFF + offB[nj], bb + nj * 4);
            #pragma unroll
            for (int mi = 0; mi < 4; mi++)
                #pragma unroll
                for (int j = 0; j < 8; j++) mma16816(acc[mi][j], ah[mi], bb + j * 2);
            #pragma unroll
            for (int mi = 0; mi < 4; mi++)
                #pragma unroll
                for (int j = 0; j < 8; j++) mma16816(acc[mi][j], al[mi], bb + j * 2);
            #pragma unroll
            for (int nj = 0; nj < 4; nj++) ldsm4(kb + BL5_OFF + offB[nj], bb + nj * 4);
            #pragma unroll
            for (int mi = 0; mi < 4; mi++)
                #pragma unroll
                for (int j = 0; j < 8; j++) mma16816(acc[mi][j], ah[mi], bb + j * 2);
        }
        __syncthreads();
    }

    constexpr int SP = BN + 4;
    float* st = (float*)smb;
    const int er = lane >> 2, ec = (lane & 3) * 2;
    #pragma unroll
    for (int mi = 0; mi < 4; mi++)
        #pragma unroll
        for (int j = 0; j < 8; j++) {
            const int r0 = wm * 64 + mi * 16 + er;
            const int c0 = wn * 64 + j * 8 + ec;
            st[r0 * SP + c0]       = acc[mi][j][0];
            st[r0 * SP + c0 + 1]   = acc[mi][j][1];
            st[(r0+8) * SP + c0]     = acc[mi][j][2];
            st[(r0+8) * SP + c0 + 1] = acc[mi][j][3];
        }
    __syncthreads();

    const float* bias = ga.bias[z] + (size_t)blockIdx.x * BN;
    #pragma unroll
    for (int jj = 0; jj < 32; jj++) {
        const int idx = tid + jj * 256;
        const int r = idx >> 5, c4 = (idx & 31) * 4;
        float4 v;
        v.x = st[r * SP + c4 + 0]; v.y = st[r * SP + c4 + 1];
        v.z = st[r * SP + c4 + 2]; v.w = st[r * SP + c4 + 3];
        if (FLAGS & F_BIAS) {
            float4 b4 = *(const float4*)(bias + c4);
            v.x += b4.x; v.y += b4.y; v.z += b4.z; v.w += b4.w;
        }
        if (FLAGS & F_RELU) {
            v.x = fmaxf(v.x, 0.f); v.y = fmaxf(v.y, 0.f);
            v.z = fmaxf(v.z, 0.f); v.w = fmaxf(v.w, 0.f);
        }
        if (FLAGS & F_QKVOUT) {
            const int token = blockIdx.y * BM + r;
            const int bb2 = token >> 10, ss = token & 1023;
            const int f = blockIdx.x * BN + c4;
            const int hh2 = f >> 6, dk = f & 63;
            __nv_bfloat16 h[4], l[4];
            split_bf16(v.x, h[0], l[0]); split_bf16(v.y, h[1], l[1]);
            split_bf16(v.z, h[2], l[2]); split_bf16(v.w, h[3], l[3]);
            if (z == 2) {
                // V: transposed layout [B,H,64,S]
                #pragma unroll
                for (int e = 0; e < 4; e++) {
                    const size_t base = (((size_t)bb2 * Hh + hh2) * DKk + dk + e) * Ssz + ss;
                    ga.Chi[z][base] = h[e];
                    ga.Clo[z][base] = l[e];
                }
            } else {
                const size_t base = (((size_t)bb2 * Hh + hh2) * Ssz + ss) * DKk + dk;
                *(uint2*)(ga.Chi[z] + base) = *(uint2*)h;
                *(uint2*)(ga.Clo[z] + base) = *(uint2*)l;
            }
        } else if (FLAGS & F_SPLITOUT) {
            const size_t base = (size_t)(blockIdx.y * BM + r) * ga.ldc + blockIdx.x * BN + c4;
            __nv_bfloat16 h[4], l[4];
            split_bf16(v.x, h[0], l[0]); split_bf16(v.y, h[1], l[1]);
            split_bf16(v.z, h[2], l[2]); split_bf16(v.w, h[3], l[3]);
            *(uint2*)(ga.Chi[z] + base) = *(uint2*)h;
            *(uint2*)(ga.Clo[z] + base) = *(uint2*)l;
        } else {
            if (FLAGS & F_RES) {
                const float* R = ga.Res + (size_t)blockIdx.y * BM * ga.ldc + (size_t)blockIdx.x * BN;
                float4 r4 = *(const float4*)(R + (size_t)r * ga.ldc + c4);
                v.x += r4.x; v.y += r4.y; v.z += r4.z; v.w += r4.w;
            }
            float* C = ga.C[z] + (size_t)blockIdx.y * BM * ga.ldc + (size_t)blockIdx.x * BN;
            *(float4*)(C + (size_t)r * ga.ldc + c4) = v;
        }
    }
}

// ===================== fused causal flash attention =========================
// grid (8 bm, 32 bh), 256 thr. Q/K head-major [B,H,S,64]; V transposed [B,H,64,S].
#define QPIT 72
#define VPIT 136
#define SQH_E 0
#define SQL_E (128*QPIT)
#define SKH_E (2*128*QPIT)
#define SKL_E (3*128*QPIT)
#define SVH_E (4*128*QPIT)
#define SVL_E (4*128*QPIT + 64*VPIT)
#define SMEM_FA ((4*128*QPIT + 2*64*VPIT) * 2)   // 108544 bytes

__global__ __launch_bounds__(256) void flash_attn_k(
    const __nv_bfloat16* __restrict__ Qh, const __nv_bfloat16* __restrict__ Ql,
    const __nv_bfloat16* __restrict__ Kh, const __nv_bfloat16* __restrict__ Kl,
    const __nv_bfloat16* __restrict__ Vth, const __nv_bfloat16* __restrict__ Vtl,
    __nv_bfloat16* __restrict__ Oh, __nv_bfloat16* __restrict__ Ol)
{
    const int bm = 7 - blockIdx.x;               // heavy tiles first
    const int bh = blockIdx.y, bb = bh >> 4, hh = bh & 15;
    extern __shared__ __nv_bfloat16 sm[];
    const int tid = threadIdx.x, wid = tid >> 5, lane = tid & 31;

    // Q tile (persistent)
    const size_t qoff = ((size_t)bh * Ssz + bm * 128) * DKk;
    #pragma unroll
    for (int s = 0; s < 4; s++) {
        const int slot = tid + s * 256;
        const int r = slot >> 3, c8 = slot & 7;
        *(uint4*)&sm[SQH_E + r * QPIT + c8 * 8] = *(const uint4*)(Qh + qoff + (size_t)r * DKk + c8 * 8);
        *(uint4*)&sm[SQL_E + r * QPIT + c8 * 8] = *(const uint4*)(Ql + qoff + (size_t)r * DKk + c8 * 8);
    }

    const uint32_t smem_b = (uint32_t)__cvta_generic_to_shared(sm);
    const uint32_t offQ = (uint32_t)((wid * 16 + (lane & 15)) * QPIT * 2 + ((lane >> 4) & 1) * 16);
    uint32_t offK[8];
    #pragma unroll
    for (int nj = 0; nj < 8; nj++)
        offK[nj] = (uint32_t)((nj * 16 + (lane & 7) + ((lane >> 4) & 1) * 8) * QPIT * 2
                              + ((lane >> 3) & 1) * 16);
    uint32_t offV[4];
    #pragma unroll
    for (int nj = 0; nj < 4; nj++)
        offV[nj] = (uint32_t)((nj * 16 + (lane & 7) + ((lane >> 4) & 1) * 8) * VPIT * 2
                              + ((lane >> 3) & 1) * 16);

    float accO[8][4];
    #pragma unroll
    for (int n = 0; n < 8; n++)
        #pragma unroll
        for (int e = 0; e < 4; e++) accO[n][e] = 0.f;
    float m0 = -3.0e38f, m1 = -3.0e38f, s0 = 0.f, s1 = 0.f;

    const int r_in = lane >> 2;
    const int row_g0 = bm * 128 + wid * 16 + r_in;     // global row (e0/e1)
    const int cb = 2 * (lane & 3);

    for (int bn = 0; bn <= bm; bn++) {
        // K tile
        const size_t koff = ((size_t)bh * Ssz + bn * 128) * DKk;
        #pragma unroll
        for (int s = 0; s < 4; s++) {
            const int slot = tid + s * 256;
            const int r = slot >> 3, c8 = slot & 7;
            *(uint4*)&sm[SKH_E + r * QPIT + c8 * 8] = *(const uint4*)(Kh + koff + (size_t)r * DKk + c8 * 8);
            *(uint4*)&sm[SKL_E + r * QPIT + c8 * 8] = *(const uint4*)(Kl + koff + (size_t)r * DKk + c8 * 8);
        }
        // V^T tile: rows dk 0..63, cols seq bn*128..+127
        const size_t voff = (size_t)bh * DKk * Ssz + bn * 128;
        #pragma unroll
        for (int s = 0; s < 4; s++) {
            const int slot = tid + s * 256;
            const int r = slot >> 4, c = slot & 15;
            *(uint4*)&sm[SVH_E + r * VPIT + c * 8] = *(const uint4*)(Vth + voff + (size_t)r * Ssz + c * 8);
            *(uint4*)&sm[SVL_E + r * VPIT + c * 8] = *(const uint4*)(Vtl + voff + (size_t)r * Ssz + c * 8);
        }
        __syncthreads();

        // S = Q @ K^T (bf16x3)
        float sacc[16][4];
        #pragma unroll
        for (int j = 0; j < 16; j++)
            #pragma unroll
            for (int e = 0; e < 4; e++) sacc[j][e] = 0.f;
        #pragma unroll
        for (int kk = 0; kk < 4; kk++) {
            uint32_t q4[4], ql4[4], kb4[4];
            ldsm4(smem_b + SQH_E * 2 + offQ + kk * 32, q4);
            ldsm4(smem_b + SQL_E * 2 + offQ + kk * 32, ql4);
            #pragma unroll
            for (int nj = 0; nj < 8; nj++) {
                ldsm4(smem_b + SKH_E * 2 + offK[nj] + kk * 32, kb4);
                mma16816(sacc[2*nj],   q4,  kb4);
                mma16816(sacc[2*nj+1], q4,  kb4 + 2);
                mma16816(sacc[2*nj],   ql4, kb4);
                mma16816(sacc[2*nj+1], ql4, kb4 + 2);
                ldsm4(smem_b + SKL_E * 2 + offK[nj] + kk * 32, kb4);
                mma16816(sacc[2*nj],   q4,  kb4);
                mma16816(sacc[2*nj+1], q4,  kb4 + 2);
            }
        }

        // scale + causal mask
        const float scale = 0.125f;
        if (bn == bm) {
            #pragma unroll
            for (int j = 0; j < 16; j++)
                #pragma unroll
                for (int e = 0; e < 4; e++) {
                    const int col = bn * 128 + j * 8 + cb + (e & 1);
                    const int row = row_g0 + ((e >= 2) ? 8 : 0);
                    sacc[j][e] = (col <= row) ? sacc[j][e] * scale : -3.0e38f;
                }
        } else {
            #pragma unroll
            for (int j = 0; j < 16; j++)
                #pragma unroll
                for (int e = 0; e < 4; e++) sacc[j][e] *= scale;
        }

        // online softmax
        float tm0 = -3.0e38f, tm1 = -3.0e38f;
        #pragma unroll
        for (int j = 0; j < 16; j++) {
            tm0 = fmaxf(tm0, fmaxf(sacc[j][0], sacc[j][1]));
            tm1 = fmaxf(tm1, fmaxf(sacc[j][2], sacc[j][3]));
        }
        tm0 = fmaxf(tm0, __shfl_xor_sync(0xffffffffu, tm0, 1));
        tm0 = fmaxf(tm0, __shfl_xor_sync(0xffffffffu, tm0, 2));
        tm1 = fmaxf(tm1, __shfl_xor_sync(0xffffffffu, tm1, 1));
        tm1 = fmaxf(tm1, __shfl_xor_sync(0xffffffffu, tm1, 2));
        const float nm0 = fmaxf(m0, tm0), nm1 = fmaxf(m1, tm1);
        const float a0 = __expf(m0 - nm0), a1 = __expf(m1 - nm1);
        m0 = nm0; m1 = nm1;
        float ps0 = 0.f, ps1 = 0.f;
        #pragma unroll
        for (int j = 0; j < 16; j++) {
            sacc[j][0] = __expf(sacc[j][0] - m0); ps0 += sacc[j][0];
            sacc[j][1] = __expf(sacc[j][1] - m0); ps0 += sacc[j][1];
            sacc[j][2] = __expf(sacc[j][2] - m1); ps1 += sacc[j][2];
            sacc[j][3] = __expf(sacc[j][3] - m1); ps1 += sacc[j][3];
        }
        s0 = s0 * a0 + ps0;
        s1 = s1 * a1 + ps1;
        #pragma unroll
        for (int n = 0; n < 8; n++) {
            accO[n][0] *= a0; accO[n][1] *= a0;
            accO[n][2] *= a1; accO[n][3] *= a1;
        }

        // O += P @ V (P from sacc registers, bf16x3)
        #pragma unroll
        for (int t = 0; t < 8; t++) {
            uint32_t ph4[4], pl4[4];
            {
                __nv_bfloat16 h0, l0, h1, l1;
                split_bf16(sacc[2*t][0], h0, l0);   split_bf16(sacc[2*t][1], h1, l1);
                ph4[0] = pack2(h0, h1); pl4[0] = pack2(l0, l1);
                split_bf16(sacc[2*t][2], h0, l0);   split_bf16(sacc[2*t][3], h1, l1);
                ph4[1] = pack2(h0, h1); pl4[1] = pack2(l0, l1);
                split_bf16(sacc[2*t+1][0], h0, l0); split_bf16(sacc[2*t+1][1], h1, l1);
                ph4[2] = pack2(h0, h1); pl4[2] = pack2(l0, l1);
                split_bf16(sacc[2*t+1][2], h0, l0); split_bf16(sacc[2*t+1][3], h1, l1);
                ph4[3] = pack2(h0, h1); pl4[3] = pack2(l0, l1);
            }
            #pragma unroll
            for (int nj = 0; nj < 4; nj++) {
                uint32_t vb[4];
                ldsm4(smem_b + SVH_E * 2 + offV[nj] + t * 32, vb);
                mma16816(accO[2*nj],   ph4, vb);
                mma16816(accO[2*nj+1], ph4, vb + 2);
                mma16816(accO[2*nj],   pl4, vb);
                mma16816(accO[2*nj+1], pl4, vb + 2);
                ldsm4(smem_b + SVL_E * 2 + offV[nj] + t * 32, vb);
                mma16816(accO[2*nj],   ph4, vb);
                mma16816(accO[2*nj+1], ph4, vb + 2);
            }
        }
        __syncthreads();     // protect K/V tiles before next bn load
    }

    // normalize + split write (token-major [B,S,D])
    s0 += __shfl_xor_sync(0xffffffffu, s0, 1);
    s0 += __shfl_xor_sync(0xffffffffu, s0, 2);
    s1 += __shfl_xor_sync(0xffffffffu, s1, 1);
    s1 += __shfl_xor_sync(0xffffffffu, s1, 2);
    const float i0 = 1.0f / s0, i1 = 1.0f / s1;
    #pragma unroll
    for (int n = 0; n < 8; n++)
        #pragma unroll
        for (int e = 0; e < 4; e++) {
            const int row = row_g0 + ((e >= 2) ? 8 : 0);
            const int col = n * 8 + cb + (e & 1);
            const float o = accO[n][e] * ((e < 2) ? i0 : i1);
            __nv_bfloat16 h, l; split_bf16(o, h, l);
            const size_t base = ((size_t)bb * Ssz + row) * Dm + hh * DKk + col;
            Oh[base] = h; Ol[base] = l;
        }
}

// ===================== embedding / layernorm (split out) ====================
__global__ __launch_bounds__(256) void embed_k(
    const int* __restrict__ ids, const float* __restrict__ tok,
    const float* __restrict__ pos, float* __restrict__ x)
{
    const int row = blockIdx.x;
    const int s   = row & (Ssz - 1);
    const int id  = ids[row];
    const int t   = threadIdx.x;
    float4 tv = *(const float4*)(tok + (size_t)id * Dm + t * 4);
    float4 pv = *(const float4*)(pos + (size_t)s  * Dm + t * 4);
    float4 o; o.x = tv.x + pv.x; o.y = tv.y + pv.y; o.z = tv.z + pv.z; o.w = tv.w + pv.w;
    *(float4*)(x + (size_t)row * Dm + t * 4) = o;
}

__global__ __launch_bounds__(256) void layernorm_split_k(
    const float* __restrict__ x, const float* __restrict__ g,
    const float* __restrict__ be,
    __nv_bfloat16* __restrict__ oh, __nv_bfloat16* __restrict__ ol)
{
    const int row = blockIdx.x;
    const int t   = threadIdx.x;
    const float* xr = x + (size_t)row * Dm;
    float4 v = *(const float4*)(xr + t * 4);
    float s  = v.x + v.y + v.z + v.w;
    float ss = v.x*v.x + v.y*v.y + v.z*v.z + v.w*v.w;
    #pragma unroll
    for (int off = 16; off; off >>= 1) {
        s  += __shfl_xor_sync(0xffffffffu, s,  off);
        ss += __shfl_xor_sync(0xffffffffu, ss, off);
    }
    __shared__ float rs[8], rss[8];
    const int warp = t >> 5, lane = t & 31;
    if (lane == 0) { rs[warp] = s; rss[warp] = ss; }
    __syncthreads();
    s = 0.f; ss = 0.f;
    #pragma unroll
    for (int i = 0; i < 8; i++) { s += rs[i]; ss += rss[i]; }
    const float mean = s  * (1.0f / Dm);
    const float var  = ss * (1.0f / Dm) - mean * mean;
    const float rstd = rsqrtf(var + 1e-5f);
    float4 gv = *(const float4*)(g  + t * 4);
    float4 bv = *(const float4*)(be + t * 4);
    float o0 = (v.x - mean) * rstd * gv.x + bv.x;
    float o1 = (v.y - mean) * rstd * gv.y + bv.y;
    float o2 = (v.z - mean) * rstd * gv.z + bv.z;
    float o3 = (v.w - mean) * rstd * gv.w + bv.w;
    __nv_bfloat16 h[4], l[4];
    split_bf16(o0, h[0], l[0]); split_bf16(o1, h[1], l[1]);
    split_bf16(o2, h[2], l[2]); split_bf16(o3, h[3], l[3]);
    *(uint2*)(oh + (size_t)row * Dm + t * 4) = *(uint2*)h;
    *(uint2*)(ol + (size_t)row * Dm + t * 4) = *(uint2*)l;
}

// ===================== driver ===============================================
extern "C" void kernel_launch(void* const* d_in, const int* in_sizes, int n_in,
                              void* d_out, int out_size)
{
    const int*   ids  = (const int*)  d_in[0];
    const float* tok  = (const float*)d_in[1];
    const float* pos  = (const float*)d_in[2];
    const float* Wq   = (const float*)d_in[3];
    const float* bq   = (const float*)d_in[4];
    const float* Wk   = (const float*)d_in[5];
    const float* bk   = (const float*)d_in[6];
    const float* Wv   = (const float*)d_in[7];
    const float* bv   = (const float*)d_in[8];
    const float* Wo   = (const float*)d_in[9];
    const float* bo   = (const float*)d_in[10];
    const float* W1   = (const float*)d_in[11];
    const float* b1   = (const float*)d_in[12];
    const float* W2   = (const float*)d_in[13];
    const float* b2   = (const float*)d_in[14];
    const float* ln1g = (const float*)d_in[15];
    const float* ln1b = (const float*)d_in[16];
    const float* ln2g = (const float*)d_in[17];
    const float* ln2b = (const float*)d_in[18];
    const float* lnfg = (const float*)d_in[19];
    const float* lnfb = (const float*)d_in[20];
    const float* Wout = (const float*)d_in[21];
    const float* bout = (const float*)d_in[22];
    float* out = (float*)d_out;

    float *x;
    __nv_bfloat16 *wc, *hh, *hl, *oh, *ol, *ffh, *ffl;
    __nv_bfloat16 *qh, *ql, *kh, *kl, *vh, *vl;
    cudaGetSymbolAddress((void**)&x,  g_x);
    cudaGetSymbolAddress((void**)&wc, g_wc);
    cudaGetSymbolAddress((void**)&hh, g_hh);   cudaGetSymbolAddress((void**)&hl, g_hl);
    cudaGetSymbolAddress((void**)&oh, g_oh);   cudaGetSymbolAddress((void**)&ol, g_ol);
    cudaGetSymbolAddress((void**)&ffh, g_ffh); cudaGetSymbolAddress((void**)&ffl, g_ffl);
    cudaGetSymbolAddress((void**)&qh, g_qh);   cudaGetSymbolAddress((void**)&ql, g_ql);
    cudaGetSymbolAddress((void**)&kh, g_kh);   cudaGetSymbolAddress((void**)&kl, g_kl);
    cudaGetSymbolAddress((void**)&vh, g_vh);   cudaGetSymbolAddress((void**)&vl, g_vl);

    cudaFuncSetAttribute(mma_gemm_k<F_BIAS|F_RES>,                cudaFuncAttributeMaxDynamicSharedMemorySize, SMEM_GM);
    cudaFuncSetAttribute(mma_gemm256_k<F_BIAS>,                   cudaFuncAttributeMaxDynamicSharedMemorySize, SMEM_GM5);
    cudaFuncSetAttribute(mma_gemm256_k<F_BIAS|F_QKVOUT>,          cudaFuncAttributeMaxDynamicSharedMemorySize, SMEM_GM5);
    cudaFuncSetAttribute(mma_gemm256_k<F_BIAS|F_RELU|F_SPLITOUT>, cudaFuncAttributeMaxDynamicSharedMemorySize, SMEM_GM5);
    cudaFuncSetAttribute(flash_attn_k, cudaFuncAttributeMaxDynamicSharedMemorySize, SMEM_FA);

    convert_w_k<<<dim3(Dm/32, Dm/32, Ll), 256>>>(Wq,   wc + OFF_Q,  Dm, Dm);
    convert_w_k<<<dim3(Dm/32, Dm/32, Ll), 256>>>(Wk,   wc + OFF_K,  Dm, Dm);
    convert_w_k<<<dim3(Dm/32, Dm/32, Ll), 256>>>(Wv,   wc + OFF_V,  Dm, Dm);
    convert_w_k<<<dim3(Dm/32, Dm/32, Ll), 256>>>(Wo,   wc + OFF_O,  Dm, Dm);
    convert_w_k<<<dim3(Ff/32, Dm/32, Ll), 256>>>(W1,   wc + OFF_W1, Dm, Ff);
    convert_w_k<<<dim3(Dm/32, Ff/32, Ll), 256>>>(W2,   wc + OFF_W2, Ff, Dm);
    convert_w_k<<<dim3(Vv/32, Dm/32, 1),  256>>>(Wout, wc + OFF_WO, Dm, Vv);

    embed_k<<<TOK, 256>>>(ids, tok, pos, x);

    const dim3 gQKV (Dm/128, TOK/256, 3);
    const dim3 gProj(Dm/128, TOK/128, 1);
    const dim3 gFfn1(Ff/128, TOK/256, 1);
    const dim3 gLogit(Vv/128, TOK/256, 1);
    const dim3 gFA(Ssz/128, BH, 1);

    for (int l = 0; l < Ll; l++) {
        const size_t oDb = (size_t)l * Dm;
        const size_t oFb = (size_t)l * Ff;
        const size_t oq = (size_t)l * SQW, o1 = (size_t)l * SW1;

        layernorm_split_k<<<TOK, 256>>>(x, ln1g + oDb, ln1b + oDb, hh, hl);

        GemmArgs qa{};
        qa.Ahi = hh; qa.Alo = hl; qa.K = Dm; qa.ldc = Dm;
        qa.Bhi[0] = wc + OFF_Q + oq; qa.Blo[0] = qa.Bhi[0] + (size_t)Dm*Dm;
        qa.Bhi[1] = wc + OFF_K + oq; qa.Blo[1] = qa.Bhi[1] + (size_t)Dm*Dm;
        qa.Bhi[2] = wc + OFF_V + oq; qa.Blo[2] = qa.Bhi[2] + (size_t)Dm*Dm;
        qa.bias[0] = bq + oDb; qa.bias[1] = bk + oDb; qa.bias[2] = bv + oDb;
        qa.Chi[0] = qh; qa.Clo[0] = ql;
        qa.Chi[1] = kh; qa.Clo[1] = kl;
        qa.Chi[2] = vh; qa.Clo[2] = vl;
        mma_gemm256_k<F_BIAS|F_QKVOUT><<<gQKV, 256, SMEM_GM5>>>(qa);

        flash_attn_k<<<gFA, 256, SMEM_FA>>>(qh, ql, kh, kl, vh, vl, oh, ol);

        GemmArgs oa{};
        oa.Ahi = oh; oa.Alo = ol; oa.K = Dm; oa.ldc = Dm;
        oa.Bhi[0] = wc + OFF_O + oq; oa.Blo[0] = oa.Bhi[0] + (size_t)Dm*Dm;
        oa.bias[0] = bo + oDb; oa.Res = x; oa.C[0] = x;
        mma_gemm_k<F_BIAS|F_RES><<<gProj, 256, SMEM_GM>>>(oa);

        layernorm_split_k<<<TOK, 256>>>(x, ln2g + oDb, ln2b + oDb, hh, hl);

        GemmArgs fa{};
        fa.Ahi = hh; fa.Alo = hl; fa.K = Dm; fa.ldc = Ff;
        fa.Bhi[0] = wc + OFF_W1 + o1; fa.Blo[0] = fa.Bhi[0] + (size_t)Dm*Ff;
        fa.bias[0] = b1 + oFb; fa.Chi[0] = ffh; fa.Clo[0] = ffl;
        mma_gemm256_k<F_BIAS|F_RELU|F_SPLITOUT><<<gFfn1, 256, SMEM_GM5>>>(fa);

        GemmArgs f2{};
        f2.Ahi = ffh; f2.Alo = ffl; f2.K = Ff; f2.ldc = Dm;
        f2.Bhi[0] = wc + OFF_W2 + o1; f2.Blo[0] = f2.Bhi[0] + (size_t)Dm*Ff;
        f2.bias[0] = b2 + oDb; f2.Res = x; f2.C[0] = x;
        mma_gemm_k<F_BIAS|F_RES><<<gProj, 256, SMEM_GM>>>(f2);
    }

    layernorm_split_k<<<TOK, 256>>>(x, lnfg, lnfb, hh, hl);

    GemmArgs la{};
    la.Ahi = hh; la.Alo = hl; la.K = Dm; la.ldc = Vv;
    la.Bhi[0] = wc + OFF_WO; la.Blo[0] = la.Bhi[0] + (size_t)Dm*Vv;
    la.bias[0] = bout; la.C[0] = out;
    mma_gemm256_k<F_BIAS><<<gLogit, 256, SMEM_GM5>>>(la);
}

// round 15
// speedup vs baseline: 1.0616x; 1.0616x over previous
#include <cuda_runtime.h>
#include <cuda_bf16.h>
#include <cstdint>
#include <cstddef>

#define Bsz 2
#define Ssz 1024
#define Dm  1024
#define Hh  16
#define DKk 64
#define Ff  4096
#define Vv  32000
#define Ll  8
#define TOK (Bsz*Ssz)
#define BH  (Bsz*Hh)

// ===================== scratch ==============================================
__device__ float g_x [TOK*Dm];
__device__ __nv_bfloat16 g_hh[TOK*Dm],  g_hl[TOK*Dm];
__device__ __nv_bfloat16 g_oh[TOK*Dm],  g_ol[TOK*Dm];
__device__ __nv_bfloat16 g_ffh[TOK*Ff], g_ffl[TOK*Ff];
__device__ __nv_bfloat16 g_qh[TOK*Dm],  g_ql[TOK*Dm];    // [B,H,S,64]
__device__ __nv_bfloat16 g_kh[TOK*Dm],  g_kl[TOK*Dm];    // [B,H,S,64]
__device__ __nv_bfloat16 g_vh[TOK*Dm],  g_vl[TOK*Dm];    // [B,H,S,64]
__device__ __nv_bfloat16 g_vth[TOK*Dm], g_vtl[TOK*Dm];   // [B,H,64,S] transposed

#define SQW ((size_t)2*Dm*Dm)
#define SW1 ((size_t)2*Dm*Ff)
#define OFF_Q  ((size_t)0)
#define OFF_K  (OFF_Q  + (size_t)Ll*SQW)
#define OFF_V  (OFF_K  + (size_t)Ll*SQW)
#define OFF_O  (OFF_V  + (size_t)Ll*SQW)
#define OFF_W1 (OFF_O  + (size_t)Ll*SQW)
#define OFF_W2 (OFF_W1 + (size_t)Ll*SW1)
#define OFF_WO (OFF_W2 + (size_t)Ll*SW1)
#define WC_TOTAL (OFF_WO + (size_t)2*Dm*Vv)
__device__ __nv_bfloat16 g_wc[WC_TOTAL];

__device__ __forceinline__ void split_bf16(float v, __nv_bfloat16& h, __nv_bfloat16& l) {
    h = __float2bfloat16(v);
    l = __float2bfloat16(v - __bfloat162float(h));
}
__device__ __forceinline__ uint32_t pack2(__nv_bfloat16 a, __nv_bfloat16 b) {
    return (uint32_t)__bfloat16_as_ushort(a) | ((uint32_t)__bfloat16_as_ushort(b) << 16);
}
// fast exp on FMA pipe: exp(x), x <= 0. clamp, 2^r Taylor deg-6, exponent bit-trick.
__device__ __forceinline__ float fexp(float x) {
    x = fmaxf(x, -80.0f);
    const float t = x * 1.4426950408889634f;
    const float f = floorf(t);
    const float r = t - f;
    float p = 1.53527593e-4f;
    p = fmaf(p, r, 1.33335581e-3f);
    p = fmaf(p, r, 9.61812911e-3f);
    p = fmaf(p, r, 5.55041087e-2f);
    p = fmaf(p, r, 2.40226507e-1f);
    p = fmaf(p, r, 6.93147182e-1f);
    p = fmaf(p, r, 1.0f);
    const float sc = __int_as_float(((int)f + 127) << 23);
    return p * sc;
}
__device__ __forceinline__ void cpa16(void* s, const void* g) {
    uint32_t sa = (uint32_t)__cvta_generic_to_shared(s);
    asm volatile("cp.async.cg.shared.global [%0], [%1], 16;" :: "r"(sa), "l"(g));
}
#define CP_COMMIT() asm volatile("cp.async.commit_group;" ::: "memory")
#define CP_WAIT1()  asm volatile("cp.async.wait_group 1;" ::: "memory")
#define CP_WAIT0()  asm volatile("cp.async.wait_group 0;" ::: "memory")

__device__ __forceinline__ void ldsm4(uint32_t addr, uint32_t* r) {
    asm volatile("ldmatrix.sync.aligned.m8n8.x4.shared.b16 {%0,%1,%2,%3}, [%4];"
        : "=r"(r[0]), "=r"(r[1]), "=r"(r[2]), "=r"(r[3]) : "r"(addr));
}
__device__ __forceinline__ void mma16816(float* d, const uint32_t* a, const uint32_t* b) {
    asm volatile("mma.sync.aligned.m16n8k16.row.col.f32.bf16.bf16.f32 "
        "{%0,%1,%2,%3}, {%4,%5,%6,%7}, {%8,%9}, {%0,%1,%2,%3};"
        : "+f"(d[0]), "+f"(d[1]), "+f"(d[2]), "+f"(d[3])
        : "r"(a[0]), "r"(a[1]), "r"(a[2]), "r"(a[3]), "r"(b[0]), "r"(b[1]));
}

// ======= weight convert: W [K,N] fp32 -> hi/lo [N,K] bf16 (transpose) =======
__global__ __launch_bounds__(256) void convert_w_k(
    const float* __restrict__ W, __nv_bfloat16* __restrict__ out, int Kd, int Nd)
{
    __shared__ float t[32][33];
    const int l = blockIdx.z;
    const float* Wl = W + (size_t)l * Kd * Nd;
    __nv_bfloat16* hi = out + (size_t)l * 2 * Kd * Nd;
    __nv_bfloat16* lo = hi + (size_t)Kd * Nd;
    const int nb = blockIdx.x * 32, kb = blockIdx.y * 32;
    const int tx = threadIdx.x & 31, ty = threadIdx.x >> 5;
    #pragma unroll
    for (int j = 0; j < 32; j += 8)
        t[ty + j][tx] = Wl[(size_t)(kb + ty + j) * Nd + nb + tx];
    __syncthreads();
    #pragma unroll
    for (int j = 0; j < 32; j += 8) {
        const int n = nb + ty + j, k = kb + tx;
        float v = t[tx][ty + j];
        __nv_bfloat16 h, l2; split_bf16(v, h, l2);
        hi[(size_t)n * Kd + k] = h;
        lo[(size_t)n * Kd + k] = l2;
    }
}

// ======= V transpose: [B,H,S,64] -> [B,H,64,S], hi+lo together =============
__global__ __launch_bounds__(256) void vtrans_k(
    const __nv_bfloat16* __restrict__ Vh, const __nv_bfloat16* __restrict__ Vl,
    __nv_bfloat16* __restrict__ Th, __nv_bfloat16* __restrict__ Tl)
{
    __shared__ __nv_bfloat16 th[64][68], tl[64][68];
    const int bh = blockIdx.y, s0 = blockIdx.x * 64;
    const int tid = threadIdx.x;
    const size_t ibase = ((size_t)bh * Ssz + s0) * DKk;
    #pragma unroll
    for (int ss = 0; ss < 4; ss++) {
        const int idx = tid + ss * 256;            // 1024 slots: r(64) x c4(16)
        const int r = idx >> 4, c4 = (idx & 15) * 4;
        *(uint2*)&th[r][c4] = *(const uint2*)(Vh + ibase + (size_t)r * DKk + c4);
        *(uint2*)&tl[r][c4] = *(const uint2*)(Vl + ibase + (size_t)r * DKk + c4);
    }
    __syncthreads();
    const size_t obase = (size_t)bh * DKk * Ssz + s0;
    #pragma unroll
    for (int ss = 0; ss < 4; ss++) {
        const int idx = tid + ss * 256;            // dk(64) x s4(16)
        const int dk = idx >> 4, s4 = (idx & 15) * 4;
        __nv_bfloat16 a[4], b[4];
        #pragma unroll
        for (int e = 0; e < 4; e++) { a[e] = th[s4 + e][dk]; b[e] = tl[s4 + e][dk]; }
        *(uint2*)(Th + obase + (size_t)dk * Ssz + s4) = *(uint2*)a;
        *(uint2*)(Tl + obase + (size_t)dk * Ssz + s4) = *(uint2*)b;
    }
}

// ===================== GEMM flags / args ====================================
#define F_BIAS 1
#define F_RES  2
#define F_RELU 4
#define F_QKVOUT 8
#define F_SPLITOUT 16

struct GemmArgs {
    const __nv_bfloat16 *Ahi, *Alo;
    const __nv_bfloat16 *Bhi[3], *Blo[3];
    const float* bias[3];
    const float* Res;
    float* C[3];
    __nv_bfloat16 *Chi[3], *Clo[3];
    int K;
    int ldc;
};

// ===================== GEMM v4: BM=128 ======================================
#define PITB 80
#define AH_OFF 0
#define AL_OFF (128*PITB)
#define BH_OFF (2*128*PITB)
#define BL_OFF (3*128*PITB)
#define STGB   (4*128*PITB)
#define SMEM_GM (3*STGB)               // 122880

template<int FLAGS>
__global__ __launch_bounds__(256) void mma_gemm_k(GemmArgs ga)
{
    constexpr int BM = 128, BN = 128, BK = 32;
    extern __shared__ __nv_bfloat16 smb[];
    char* smc = (char*)smb;

    const int tid = threadIdx.x, wid = tid >> 5, lane = tid & 31;
    const int z = blockIdx.z;
    const int Kd = ga.K;
    const __nv_bfloat16* Ah = ga.Ahi + (size_t)blockIdx.y * BM * Kd;
    const __nv_bfloat16* Al = ga.Alo + (size_t)blockIdx.y * BM * Kd;
    const __nv_bfloat16* Bh = ga.Bhi[z] + (size_t)blockIdx.x * BN * Kd;
    const __nv_bfloat16* Bl = ga.Blo[z] + (size_t)blockIdx.x * BN * Kd;
    const int wm = wid & 3, wn = wid >> 2;

    auto stage_load = [&](int buf, int k0) {
        char* s = smc + buf * STGB;
        #pragma unroll
        for (int ss = 0; ss < 2; ss++) {
            const int slot = tid + ss * 256;
            const int r = slot >> 2, c = slot & 3;
            cpa16(s + AH_OFF + r * PITB + c * 16, Ah + (size_t)r * Kd + k0 + c * 8);
            cpa16(s + AL_OFF + r * PITB + c * 16, Al + (size_t)r * Kd + k0 + c * 8);
        }
        #pragma unroll
        for (int ss = 0; ss < 2; ss++) {
            const int slot = tid + ss * 256;
            const int r = slot >> 2, c = slot & 3;
            cpa16(s + BH_OFF + r * PITB + c * 16, Bh + (size_t)r * Kd + k0 + c * 8);
            cpa16(s + BL_OFF + r * PITB + c * 16, Bl + (size_t)r * Kd + k0 + c * 8);
        }
        CP_COMMIT();
    };

    uint32_t offA[2];
    #pragma unroll
    for (int ii = 0; ii < 2; ii++)
        offA[ii] = (uint32_t)((wm * 32 + ii * 16 + (lane & 15)) * PITB + ((lane >> 4) & 1) * 16);
    uint32_t offB[4];
    #pragma unroll
    for (int jj = 0; jj < 4; jj++)
        offB[jj] = (uint32_t)((wn * 64 + jj * 16 + (lane & 7) + ((lane >> 4) & 1) * 8) * PITB
                              + ((lane >> 3) & 1) * 16);

    const uint32_t smem_u32 = (uint32_t)__cvta_generic_to_shared(smc);

    float acc[2][8][4];
    #pragma unroll
    for (int i = 0; i < 2; i++)
        #pragma unroll
        for (int j = 0; j < 8; j++)
            #pragma unroll
            for (int e = 0; e < 4; e++) acc[i][j][e] = 0.f;

    const int nst = Kd / BK;
    stage_load(0, 0);
    stage_load(1, BK);
    for (int i = 0; i < nst; i++) {
        if (i + 1 < nst) { CP_WAIT1(); } else { CP_WAIT0(); }
        __syncthreads();
        if (i + 2 < nst) stage_load((i + 2) % 3, (i + 2) * BK);
        const uint32_t sb = smem_u32 + (uint32_t)((i % 3) * STGB);
        #pragma unroll
        for (int kk = 0; kk < BK; kk += 16) {
            const uint32_t kb = sb + kk * 2;
            uint32_t ah[2][4], al[2][4], bh[16], bl[16];
            #pragma unroll
            for (int ii = 0; ii < 2; ii++) {
                ldsm4(kb + AH_OFF + offA[ii], ah[ii]);
                ldsm4(kb + AL_OFF + offA[ii], al[ii]);
            }
            #pragma unroll
            for (int jj = 0; jj < 4; jj++) {
                ldsm4(kb + BH_OFF + offB[jj], bh + jj * 4);
                ldsm4(kb + BL_OFF + offB[jj], bl + jj * 4);
            }
            #pragma unroll
            for (int ii = 0; ii < 2; ii++)
                #pragma unroll
                for (int j = 0; j < 8; j++) mma16816(acc[ii][j], ah[ii], bh + j * 2);
            #pragma unroll
            for (int ii = 0; ii < 2; ii++)
                #pragma unroll
                for (int j = 0; j < 8; j++) mma16816(acc[ii][j], ah[ii], bl + j * 2);
            #pragma unroll
            for (int ii = 0; ii < 2; ii++)
                #pragma unroll
                for (int j = 0; j < 8; j++) mma16816(acc[ii][j], al[ii], bh + j * 2);
        }
        __syncthreads();
    }

    constexpr int SP = BN + 4;
    float* st = (float*)smb;
    const int er = lane >> 2, ec = (lane & 3) * 2;
    #pragma unroll
    for (int ii = 0; ii < 2; ii++)
        #pragma unroll
        for (int j = 0; j < 8; j++) {
            const int r0 = wm * 32 + ii * 16 + er;
            const int c0 = wn * 64 + j * 8 + ec;
            st[r0 * SP + c0]       = acc[ii][j][0];
            st[r0 * SP + c0 + 1]   = acc[ii][j][1];
            st[(r0+8) * SP + c0]     = acc[ii][j][2];
            st[(r0+8) * SP + c0 + 1] = acc[ii][j][3];
        }
    __syncthreads();

    const float* bias = ga.bias[z] + (size_t)blockIdx.x * BN;
    #pragma unroll
    for (int jj = 0; jj < 16; jj++) {
        const int idx = tid + jj * 256;
        const int r = idx >> 5, c4 = (idx & 31) * 4;
        float4 v;
        v.x = st[r * SP + c4 + 0]; v.y = st[r * SP + c4 + 1];
        v.z = st[r * SP + c4 + 2]; v.w = st[r * SP + c4 + 3];
        if (FLAGS & F_BIAS) {
            float4 b4 = *(const float4*)(bias + c4);
            v.x += b4.x; v.y += b4.y; v.z += b4.z; v.w += b4.w;
        }
        if (FLAGS & F_RELU) {
            v.x = fmaxf(v.x, 0.f); v.y = fmaxf(v.y, 0.f);
            v.z = fmaxf(v.z, 0.f); v.w = fmaxf(v.w, 0.f);
        }
        if (FLAGS & F_SPLITOUT) {
            const size_t base = (size_t)(blockIdx.y * BM + r) * ga.ldc + blockIdx.x * BN + c4;
            __nv_bfloat16 h[4], l[4];
            split_bf16(v.x, h[0], l[0]); split_bf16(v.y, h[1], l[1]);
            split_bf16(v.z, h[2], l[2]); split_bf16(v.w, h[3], l[3]);
            *(uint2*)(ga.Chi[z] + base) = *(uint2*)h;
            *(uint2*)(ga.Clo[z] + base) = *(uint2*)l;
        } else {
            if (FLAGS & F_RES) {
                const float* R = ga.Res + (size_t)blockIdx.y * BM * ga.ldc + (size_t)blockIdx.x * BN;
                float4 r4 = *(const float4*)(R + (size_t)r * ga.ldc + c4);
                v.x += r4.x; v.y += r4.y; v.z += r4.z; v.w += r4.w;
            }
            float* C = ga.C[z] + (size_t)blockIdx.y * BM * ga.ldc + (size_t)blockIdx.x * BN;
            *(float4*)(C + (size_t)r * ga.ldc + c4) = v;
        }
    }
}

// ===================== GEMM v5: BM=256, warp tile 64x64 =====================
#define AH5_OFF 0
#define AL5_OFF (256*PITB)
#define BH5_OFF (2*256*PITB)
#define BL5_OFF (2*256*PITB + 128*PITB)
#define STGB5   (2*256*PITB + 2*128*PITB)
#define SMEM_GM5 (3*STGB5)                   // 184320

template<int FLAGS>
__global__ __launch_bounds__(256) void mma_gemm256_k(GemmArgs ga)
{
    constexpr int BM = 256, BN = 128, BK = 32;
    extern __shared__ __nv_bfloat16 smb[];
    char* smc = (char*)smb;

    const int tid = threadIdx.x, wid = tid >> 5, lane = tid & 31;
    const int z = blockIdx.z;
    const int Kd = ga.K;
    const __nv_bfloat16* Ah = ga.Ahi + (size_t)blockIdx.y * BM * Kd;
    const __nv_bfloat16* Al = ga.Alo + (size_t)blockIdx.y * BM * Kd;
    const __nv_bfloat16* Bh = ga.Bhi[z] + (size_t)blockIdx.x * BN * Kd;
    const __nv_bfloat16* Bl = ga.Blo[z] + (size_t)blockIdx.x * BN * Kd;
    const int wm = wid & 3, wn = wid >> 2;

    auto stage_load = [&](int buf, int k0) {
        char* s = smc + buf * STGB5;
        #pragma unroll
        for (int ss = 0; ss < 4; ss++) {
            const int slot = tid + ss * 256;
            const int r = slot >> 2, c = slot & 3;
            cpa16(s + AH5_OFF + r * PITB + c * 16, Ah + (size_t)r * Kd + k0 + c * 8);
            cpa16(s + AL5_OFF + r * PITB + c * 16, Al + (size_t)r * Kd + k0 + c * 8);
        }
        #pragma unroll
        for (int ss = 0; ss < 2; ss++) {
            const int slot = tid + ss * 256;
            const int r = slot >> 2, c = slot & 3;
            cpa16(s + BH5_OFF + r * PITB + c * 16, Bh + (size_t)r * Kd + k0 + c * 8);
            cpa16(s + BL5_OFF + r * PITB + c * 16, Bl + (size_t)r * Kd + k0 + c * 8);
        }
        CP_COMMIT();
    };

    uint32_t offA[4];
    #pragma unroll
    for (int mi = 0; mi < 4; mi++)
        offA[mi] = (uint32_t)((wm * 64 + mi * 16 + (lane & 15)) * PITB + ((lane >> 4) & 1) * 16);
    uint32_t offB[4];
    #pragma unroll
    for (int nj = 0; nj < 4; nj++)
        offB[nj] = (uint32_t)((wn * 64 + nj * 16 + (lane & 7) + ((lane >> 4) & 1) * 8) * PITB
                              + ((lane >> 3) & 1) * 16);

    const uint32_t smem_u32 = (uint32_t)__cvta_generic_to_shared(smc);

    float acc[4][8][4];
    #pragma unroll
    for (int i = 0; i < 4; i++)
        #pragma unroll
        for (int j = 0; j < 8; j++)
            #pragma unroll
            for (int e = 0; e < 4; e++) acc[i][j][e] = 0.f;

    const int nst = Kd / BK;
    stage_load(0, 0);
    stage_load(1, BK);
    for (int i = 0; i < nst; i++) {
        if (i + 1 < nst) { CP_WAIT1(); } else { CP_WAIT0(); }
        __syncthreads();
        if (i + 2 < nst) stage_load((i + 2) % 3, (i + 2) * BK);
        const uint32_t sb = smem_u32 + (uint32_t)((i % 3) * STGB5);
        #pragma unroll
        for (int kk = 0; kk < BK; kk += 16) {
            const uint32_t kb = sb + kk * 2;
            uint32_t ah[4][4], al[4][4], bb[16];
            #pragma unroll
            for (int mi = 0; mi < 4; mi++) {
                ldsm4(kb + AH5_OFF + offA[mi], ah[mi]);
                ldsm4(kb + AL5_OFF + offA[mi], al[mi]);
            }
            #pragma unroll
            for (int nj = 0; nj < 4; nj++) ldsm4(kb + BH5_OFF + offB[nj], bb + nj * 4);
            #pragma unroll
            for (int mi = 0; mi < 4; mi++)
                #pragma unroll
                for (int j = 0; j < 8; j++) mma16816(acc[mi][j], ah[mi], bb + j * 2);
            #pragma unroll
            for (int mi = 0; mi < 4; mi++)
                #pragma unroll
                for (int j = 0; j < 8; j++) mma16816(acc[mi][j], al[mi], bb + j * 2);
            #pragma unroll
            for (int nj = 0; nj < 4; nj++) ldsm4(kb + BL5_OFF + offB[nj], bb + nj * 4);
            #pragma unroll
            for (int mi = 0; mi < 4; mi++)
                #pragma unroll
                for (int j = 0; j < 8; j++) mma16816(acc[mi][j], ah[mi], bb + j * 2);
        }
        __syncthreads();
    }

    constexpr int SP = BN + 4;
    float* st = (float*)smb;
    const int er = lane >> 2, ec = (lane & 3) * 2;
    #pragma unroll
    for (int mi = 0; mi < 4; mi++)
        #pragma unroll
        for (int j = 0; j < 8; j++) {
            const int r0 = wm * 64 + mi * 16 + er;
            const int c0 = wn * 64 + j * 8 + ec;
            st[r0 * SP + c0]       = acc[mi][j][0];
            st[r0 * SP + c0 + 1]   = acc[mi][j][1];
            st[(r0+8) * SP + c0]     = acc[mi][j][2];
            st[(r0+8) * SP + c0 + 1] = acc[mi][j][3];
        }
    __syncthreads();

    const float* bias = ga.bias[z] + (size_t)blockIdx.x * BN;
    #pragma unroll
    for (int jj = 0; jj < 32; jj++) {
        const int idx = tid + jj * 256;
        const int r = idx >> 5, c4 = (idx & 31) * 4;
        float4 v;
        v.x = st[r * SP + c4 + 0]; v.y = st[r * SP + c4 + 1];
        v.z = st[r * SP + c4 + 2]; v.w = st[r * SP + c4 + 3];
        if (FLAGS & F_BIAS) {
            float4 b4 = *(const float4*)(bias + c4);
            v.x += b4.x; v.y += b4.y; v.z += b4.z; v.w += b4.w;
        }
        if (FLAGS & F_RELU) {
            v.x = fmaxf(v.x, 0.f); v.y = fmaxf(v.y, 0.f);
            v.z = fmaxf(v.z, 0.f); v.w = fmaxf(v.w, 0.f);
        }
        if (FLAGS & F_QKVOUT) {
            const int token = blockIdx.y * BM + r;
            const int bb2 = token >> 10, ss = token & 1023;
            const int f = blockIdx.x * BN + c4;
            const int hh2 = f >> 6, dk = f & 63;
            const size_t base = (((size_t)bb2 * Hh + hh2) * Ssz + ss) * DKk + dk;
            __nv_bfloat16 h[4], l[4];
            split_bf16(v.x, h[0], l[0]); split_bf16(v.y, h[1], l[1]);
            split_bf16(v.z, h[2], l[2]); split_bf16(v.w, h[3], l[3]);
            *(uint2*)(ga.Chi[z] + base) = *(uint2*)h;
            *(uint2*)(ga.Clo[z] + base) = *(uint2*)l;
        } else if (FLAGS & F_SPLITOUT) {
            const size_t base = (size_t)(blockIdx.y * BM + r) * ga.ldc + blockIdx.x * BN + c4;
            __nv_bfloat16 h[4], l[4];
            split_bf16(v.x, h[0], l[0]); split_bf16(v.y, h[1], l[1]);
            split_bf16(v.z, h[2], l[2]); split_bf16(v.w, h[3], l[3]);
            *(uint2*)(ga.Chi[z] + base) = *(uint2*)h;
            *(uint2*)(ga.Clo[z] + base) = *(uint2*)l;
        } else {
            if (FLAGS & F_RES) {
                const float* R = ga.Res + (size_t)blockIdx.y * BM * ga.ldc + (size_t)blockIdx.x * BN;
                float4 r4 = *(const float4*)(R + (size_t)r * ga.ldc + c4);
                v.x += r4.x; v.y += r4.y; v.z += r4.z; v.w += r4.w;
            }
            float* C = ga.C[z] + (size_t)blockIdx.y * BM * ga.ldc + (size_t)blockIdx.x * BN;
            *(float4*)(C + (size_t)r * ga.ldc + c4) = v;
        }
    }
}

// ===================== fused causal flash attention =========================
#define QPIT 72
#define VPIT 136
#define SQH_E 0
#define SQL_E (128*QPIT)
#define SKH_E (2*128*QPIT)
#define SKL_E (3*128*QPIT)
#define SVH_E (4*128*QPIT)
#define SVL_E (4*128*QPIT + 64*VPIT)
#define SMEM_FA ((4*128*QPIT + 2*64*VPIT) * 2)   // 108544 bytes

__global__ __launch_bounds__(256) void flash_attn_k(
    const __nv_bfloat16* __restrict__ Qh, const __nv_bfloat16* __restrict__ Ql,
    const __nv_bfloat16* __restrict__ Kh, const __nv_bfloat16* __restrict__ Kl,
    const __nv_bfloat16* __restrict__ Vth, const __nv_bfloat16* __restrict__ Vtl,
    __nv_bfloat16* __restrict__ Oh, __nv_bfloat16* __restrict__ Ol)
{
    const int bm = 7 - blockIdx.x;
    const int bh = blockIdx.y, bb = bh >> 4, hh = bh & 15;
    extern __shared__ __nv_bfloat16 sm[];
    const int tid = threadIdx.x, wid = tid >> 5, lane = tid & 31;

    const size_t qoff = ((size_t)bh * Ssz + bm * 128) * DKk;
    #pragma unroll
    for (int s = 0; s < 4; s++) {
        const int slot = tid + s * 256;
        const int r = slot >> 3, c8 = slot & 7;
        *(uint4*)&sm[SQH_E + r * QPIT + c8 * 8] = *(const uint4*)(Qh + qoff + (size_t)r * DKk + c8 * 8);
        *(uint4*)&sm[SQL_E + r * QPIT + c8 * 8] = *(const uint4*)(Ql + qoff + (size_t)r * DKk + c8 * 8);
    }

    const uint32_t smem_b = (uint32_t)__cvta_generic_to_shared(sm);
    const uint32_t offQ = (uint32_t)((wid * 16 + (lane & 15)) * QPIT * 2 + ((lane >> 4) & 1) * 16);
    uint32_t offK[8];
    #pragma unroll
    for (int nj = 0; nj < 8; nj++)
        offK[nj] = (uint32_t)((nj * 16 + (lane & 7) + ((lane >> 4) & 1) * 8) * QPIT * 2
                              + ((lane >> 3) & 1) * 16);
    uint32_t offV[4];
    #pragma unroll
    for (int nj = 0; nj < 4; nj++)
        offV[nj] = (uint32_t)((nj * 16 + (lane & 7) + ((lane >> 4) & 1) * 8) * VPIT * 2
                              + ((lane >> 3) & 1) * 16);

    float accO[8][4];
    #pragma unroll
    for (int n = 0; n < 8; n++)
        #pragma unroll
        for (int e = 0; e < 4; e++) accO[n][e] = 0.f;
    float m0 = -3.0e38f, m1 = -3.0e38f, s0 = 0.f, s1 = 0.f;

    const int r_in = lane >> 2;
    const int row_g0 = bm * 128 + wid * 16 + r_in;
    const int cb = 2 * (lane & 3);

    for (int bn = 0; bn <= bm; bn++) {
        const size_t koff = ((size_t)bh * Ssz + bn * 128) * DKk;
        #pragma unroll
        for (int s = 0; s < 4; s++) {
            const int slot = tid + s * 256;
            const int r = slot >> 3, c8 = slot & 7;
            *(uint4*)&sm[SKH_E + r * QPIT + c8 * 8] = *(const uint4*)(Kh + koff + (size_t)r * DKk + c8 * 8);
            *(uint4*)&sm[SKL_E + r * QPIT + c8 * 8] = *(const uint4*)(Kl + koff + (size_t)r * DKk + c8 * 8);
        }
        const size_t voff = (size_t)bh * DKk * Ssz + bn * 128;
        #pragma unroll
        for (int s = 0; s < 4; s++) {
            const int slot = tid + s * 256;
            const int r = slot >> 4, c = slot & 15;
            *(uint4*)&sm[SVH_E + r * VPIT + c * 8] = *(const uint4*)(Vth + voff + (size_t)r * Ssz + c * 8);
            *(uint4*)&sm[SVL_E + r * VPIT + c * 8] = *(const uint4*)(Vtl + voff + (size_t)r * Ssz + c * 8);
        }
        __syncthreads();

        float sacc[16][4];
        #pragma unroll
        for (int j = 0; j < 16; j++)
            #pragma unroll
            for (int e = 0; e < 4; e++) sacc[j][e] = 0.f;
        #pragma unroll
        for (int kk = 0; kk < 4; kk++) {
            uint32_t q4[4], ql4[4], kb4[4];
            ldsm4(smem_b + SQH_E * 2 + offQ + kk * 32, q4);
            ldsm4(smem_b + SQL_E * 2 + offQ + kk * 32, ql4);
            #pragma unroll
            for (int nj = 0; nj < 8; nj++) {
                ldsm4(smem_b + SKH_E * 2 + offK[nj] + kk * 32, kb4);
                mma16816(sacc[2*nj],   q4,  kb4);
                mma16816(sacc[2*nj+1], q4,  kb4 + 2);
                mma16816(sacc[2*nj],   ql4, kb4);
                mma16816(sacc[2*nj+1], ql4, kb4 + 2);
                ldsm4(smem_b + SKL_E * 2 + offK[nj] + kk * 32, kb4);
                mma16816(sacc[2*nj],   q4,  kb4);
                mma16816(sacc[2*nj+1], q4,  kb4 + 2);
            }
        }

        const float scale = 0.125f;
        if (bn == bm) {
            #pragma unroll
            for (int j = 0; j < 16; j++)
                #pragma unroll
                for (int e = 0; e < 4; e++) {
                    const int col = bn * 128 + j * 8 + cb + (e & 1);
                    const int row = row_g0 + ((e >= 2) ? 8 : 0);
                    sacc[j][e] = (col <= row) ? sacc[j][e] * scale : -3.0e38f;
                }
        } else {
            #pragma unroll
            for (int j = 0; j < 16; j++)
                #pragma unroll
                for (int e = 0; e < 4; e++) sacc[j][e] *= scale;
        }

        // online softmax (poly exp, no MUFU)
        float tm0 = -3.0e38f, tm1 = -3.0e38f;
        #pragma unroll
        for (int j = 0; j < 16; j++) {
            tm0 = fmaxf(tm0, fmaxf(sacc[j][0], sacc[j][1]));
            tm1 = fmaxf(tm1, fmaxf(sacc[j][2], sacc[j][3]));
        }
        tm0 = fmaxf(tm0, __shfl_xor_sync(0xffffffffu, tm0, 1));
        tm0 = fmaxf(tm0, __shfl_xor_sync(0xffffffffu, tm0, 2));
        tm1 = fmaxf(tm1, __shfl_xor_sync(0xffffffffu, tm1, 1));
        tm1 = fmaxf(tm1, __shfl_xor_sync(0xffffffffu, tm1, 2));
        const float nm0 = fmaxf(m0, tm0), nm1 = fmaxf(m1, tm1);
        const float a0 = fexp(m0 - nm0), a1 = fexp(m1 - nm1);
        m0 = nm0; m1 = nm1;
        float ps0 = 0.f, ps1 = 0.f;
        #pragma unroll
        for (int j = 0; j < 16; j++) {
            sacc[j][0] = fexp(sacc[j][0] - m0); ps0 += sacc[j][0];
            sacc[j][1] = fexp(sacc[j][1] - m0); ps0 += sacc[j][1];
            sacc[j][2] = fexp(sacc[j][2] - m1); ps1 += sacc[j][2];
            sacc[j][3] = fexp(sacc[j][3] - m1); ps1 += sacc[j][3];
        }
        s0 = s0 * a0 + ps0;
        s1 = s1 * a1 + ps1;
        #pragma unroll
        for (int n = 0; n < 8; n++) {
            accO[n][0] *= a0; accO[n][1] *= a0;
            accO[n][2] *= a1; accO[n][3] *= a1;
        }

        #pragma unroll
        for (int t = 0; t < 8; t++) {
            uint32_t ph4[4], pl4[4];
            {
                __nv_bfloat16 h0, l0, h1, l1;
                split_bf16(sacc[2*t][0], h0, l0);   split_bf16(sacc[2*t][1], h1, l1);
                ph4[0] = pack2(h0, h1); pl4[0] = pack2(l0, l1);
                split_bf16(sacc[2*t][2], h0, l0);   split_bf16(sacc[2*t][3], h1, l1);
                ph4[1] = pack2(h0, h1); pl4[1] = pack2(l0, l1);
                split_bf16(sacc[2*t+1][0], h0, l0); split_bf16(sacc[2*t+1][1], h1, l1);
                ph4[2] = pack2(h0, h1); pl4[2] = pack2(l0, l1);
                split_bf16(sacc[2*t+1][2], h0, l0); split_bf16(sacc[2*t+1][3], h1, l1);
                ph4[3] = pack2(h0, h1); pl4[3] = pack2(l0, l1);
            }
            #pragma unroll
            for (int nj = 0; nj < 4; nj++) {
                uint32_t vb[4];
                ldsm4(smem_b + SVH_E * 2 + offV[nj] + t * 32, vb);
                mma16816(accO[2*nj],   ph4, vb);
                mma16816(accO[2*nj+1], ph4, vb + 2);
                mma16816(accO[2*nj],   pl4, vb);
                mma16816(accO[2*nj+1], pl4, vb + 2);
                ldsm4(smem_b + SVL_E * 2 + offV[nj] + t * 32, vb);
                mma16816(accO[2*nj],   ph4, vb);
                mma16816(accO[2*nj+1], ph4, vb + 2);
            }
        }
        __syncthreads();
    }

    s0 += __shfl_xor_sync(0xffffffffu, s0, 1);
    s0 += __shfl_xor_sync(0xffffffffu, s0, 2);
    s1 += __shfl_xor_sync(0xffffffffu, s1, 1);
    s1 += __shfl_xor_sync(0xffffffffu, s1, 2);
    const float i0 = 1.0f / s0, i1 = 1.0f / s1;
    #pragma unroll
    for (int n = 0; n < 8; n++)
        #pragma unroll
        for (int e = 0; e < 4; e++) {
            const int row = row_g0 + ((e >= 2) ? 8 : 0);
            const int col = n * 8 + cb + (e & 1);
            const float o = accO[n][e] * ((e < 2) ? i0 : i1);
            __nv_bfloat16 h, l; split_bf16(o, h, l);
            const size_t base = ((size_t)bb * Ssz + row) * Dm + hh * DKk + col;
            Oh[base] = h; Ol[base] = l;
        }
}

// ===================== embedding / layernorm (split out) ====================
__global__ __launch_bounds__(256) void embed_k(
    const int* __restrict__ ids, const float* __restrict__ tok,
    const float* __restrict__ pos, float* __restrict__ x)
{
    const int row = blockIdx.x;
    const int s   = row & (Ssz - 1);
    const int id  = ids[row];
    const int t   = threadIdx.x;
    float4 tv = *(const float4*)(tok + (size_t)id * Dm + t * 4);
    float4 pv = *(const float4*)(pos + (size_t)s  * Dm + t * 4);
    float4 o; o.x = tv.x + pv.x; o.y = tv.y + pv.y; o.z = tv.z + pv.z; o.w = tv.w + pv.w;
    *(float4*)(x + (size_t)row * Dm + t * 4) = o;
}

__global__ __launch_bounds__(256) void layernorm_split_k(
    const float* __restrict__ x, const float* __restrict__ g,
    const float* __restrict__ be,
    __nv_bfloat16* __restrict__ oh, __nv_bfloat16* __restrict__ ol)
{
    const int row = blockIdx.x;
    const int t   = threadIdx.x;
    const float* xr = x + (size_t)row * Dm;
    float4 v = *(const float4*)(xr + t * 4);
    float s  = v.x + v.y + v.z + v.w;
    float ss = v.x*v.x + v.y*v.y + v.z*v.z + v.w*v.w;
    #pragma unroll
    for (int off = 16; off; off >>= 1) {
        s  += __shfl_xor_sync(0xffffffffu, s,  off);
        ss += __shfl_xor_sync(0xffffffffu, ss, off);
    }
    __shared__ float rs[8], rss[8];
    const int warp = t >> 5, lane = t & 31;
    if (lane == 0) { rs[warp] = s; rss[warp] = ss; }
    __syncthreads();
    s = 0.f; ss = 0.f;
    #pragma unroll
    for (int i = 0; i < 8; i++) { s += rs[i]; ss += rss[i]; }
    const float mean = s  * (1.0f / Dm);
    const float var  = ss * (1.0f / Dm) - mean * mean;
    const float rstd = rsqrtf(var + 1e-5f);
    float4 gv = *(const float4*)(g  + t * 4);
    float4 bv = *(const float4*)(be + t * 4);
    float o0 = (v.x - mean) * rstd * gv.x + bv.x;
    float o1 = (v.y - mean) * rstd * gv.y + bv.y;
    float o2 = (v.z - mean) * rstd * gv.z + bv.z;
    float o3 = (v.w - mean) * rstd * gv.w + bv.w;
    __nv_bfloat16 h[4], l[4];
    split_bf16(o0, h[0], l[0]); split_bf16(o1, h[1], l[1]);
    split_bf16(o2, h[2], l[2]); split_bf16(o3, h[3], l[3]);
    *(uint2*)(oh + (size_t)row * Dm + t * 4) = *(uint2*)h;
    *(uint2*)(ol + (size_t)row * Dm + t * 4) = *(uint2*)l;
}

// ===================== driver ===============================================
extern "C" void kernel_launch(void* const* d_in, const int* in_sizes, int n_in,
                              void* d_out, int out_size)
{
    const int*   ids  = (const int*)  d_in[0];
    const float* tok  = (const float*)d_in[1];
    const float* pos  = (const float*)d_in[2];
    const float* Wq   = (const float*)d_in[3];
    const float* bq   = (const float*)d_in[4];
    const float* Wk   = (const float*)d_in[5];
    const float* bk   = (const float*)d_in[6];
    const float* Wv   = (const float*)d_in[7];
    const float* bv   = (const float*)d_in[8];
    const float* Wo   = (const float*)d_in[9];
    const float* bo   = (const float*)d_in[10];
    const float* W1   = (const float*)d_in[11];
    const float* b1   = (const float*)d_in[12];
    const float* W2   = (const float*)d_in[13];
    const float* b2   = (const float*)d_in[14];
    const float* ln1g = (const float*)d_in[15];
    const float* ln1b = (const float*)d_in[16];
    const float* ln2g = (const float*)d_in[17];
    const float* ln2b = (const float*)d_in[18];
    const float* lnfg = (const float*)d_in[19];
    const float* lnfb = (const float*)d_in[20];
    const float* Wout = (const float*)d_in[21];
    const float* bout = (const float*)d_in[22];
    float* out = (float*)d_out;

    float *x;
    __nv_bfloat16 *wc, *hh, *hl, *oh, *ol, *ffh, *ffl;
    __nv_bfloat16 *qh, *ql, *kh, *kl, *vh, *vl, *vth, *vtl;
    cudaGetSymbolAddress((void**)&x,  g_x);
    cudaGetSymbolAddress((void**)&wc, g_wc);
    cudaGetSymbolAddress((void**)&hh, g_hh);   cudaGetSymbolAddress((void**)&hl, g_hl);
    cudaGetSymbolAddress((void**)&oh, g_oh);   cudaGetSymbolAddress((void**)&ol, g_ol);
    cudaGetSymbolAddress((void**)&ffh, g_ffh); cudaGetSymbolAddress((void**)&ffl, g_ffl);
    cudaGetSymbolAddress((void**)&qh, g_qh);   cudaGetSymbolAddress((void**)&ql, g_ql);
    cudaGetSymbolAddress((void**)&kh, g_kh);   cudaGetSymbolAddress((void**)&kl, g_kl);
    cudaGetSymbolAddress((void**)&vh, g_vh);   cudaGetSymbolAddress((void**)&vl, g_vl);
    cudaGetSymbolAddress((void**)&vth, g_vth); cudaGetSymbolAddress((void**)&vtl, g_vtl);

    cudaFuncSetAttribute(mma_gemm_k<F_BIAS|F_RES>,                cudaFuncAttributeMaxDynamicSharedMemorySize, SMEM_GM);
    cudaFuncSetAttribute(mma_gemm256_k<F_BIAS>,                   cudaFuncAttributeMaxDynamicSharedMemorySize, SMEM_GM5);
    cudaFuncSetAttribute(mma_gemm256_k<F_BIAS|F_QKVOUT>,          cudaFuncAttributeMaxDynamicSharedMemorySize, SMEM_GM5);
    cudaFuncSetAttribute(mma_gemm256_k<F_BIAS|F_RELU|F_SPLITOUT>, cudaFuncAttributeMaxDynamicSharedMemorySize, SMEM_GM5);
    cudaFuncSetAttribute(flash_attn_k, cudaFuncAttributeMaxDynamicSharedMemorySize, SMEM_FA);

    convert_w_k<<<dim3(Dm/32, Dm/32, Ll), 256>>>(Wq,   wc + OFF_Q,  Dm, Dm);
    convert_w_k<<<dim3(Dm/32, Dm/32, Ll), 256>>>(Wk,   wc + OFF_K,  Dm, Dm);
    convert_w_k<<<dim3(Dm/32, Dm/32, Ll), 256>>>(Wv,   wc + OFF_V,  Dm, Dm);
    convert_w_k<<<dim3(Dm/32, Dm/32, Ll), 256>>>(Wo,   wc + OFF_O,  Dm, Dm);
    convert_w_k<<<dim3(Ff/32, Dm/32, Ll), 256>>>(W1,   wc + OFF_W1, Dm, Ff);
    convert_w_k<<<dim3(Dm/32, Ff/32, Ll), 256>>>(W2,   wc + OFF_W2, Ff, Dm);
    convert_w_k<<<dim3(Vv/32, Dm/32, 1),  256>>>(Wout, wc + OFF_WO, Dm, Vv);

    embed_k<<<TOK, 256>>>(ids, tok, pos, x);

    const dim3 gQKV (Dm/128, TOK/256, 3);
    const dim3 gProj(Dm/128, TOK/128, 1);
    const dim3 gFfn1(Ff/128, TOK/256, 1);
    const dim3 gLogit(Vv/128, TOK/256, 1);
    const dim3 gFA(Ssz/128, BH, 1);
    const dim3 gVT(Ssz/64, BH, 1);

    for (int l = 0; l < Ll; l++) {
        const size_t oDb = (size_t)l * Dm;
        const size_t oFb = (size_t)l * Ff;
        const size_t oq = (size_t)l * SQW, o1 = (size_t)l * SW1;

        layernorm_split_k<<<TOK, 256>>>(x, ln1g + oDb, ln1b + oDb, hh, hl);

        GemmArgs qa{};
        qa.Ahi = hh; qa.Alo = hl; qa.K = Dm; qa.ldc = Dm;
        qa.Bhi[0] = wc + OFF_Q + oq; qa.Blo[0] = qa.Bhi[0] + (size_t)Dm*Dm;
        qa.Bhi[1] = wc + OFF_K + oq; qa.Blo[1] = qa.Bhi[1] + (size_t)Dm*Dm;
        qa.Bhi[2] = wc + OFF_V + oq; qa.Blo[2] = qa.Bhi[2] + (size_t)Dm*Dm;
        qa.bias[0] = bq + oDb; qa.bias[1] = bk + oDb; qa.bias[2] = bv + oDb;
        qa.Chi[0] = qh; qa.Clo[0] = ql;
        qa.Chi[1] = kh; qa.Clo[1] = kl;
        qa.Chi[2] = vh; qa.Clo[2] = vl;
        mma_gemm256_k<F_BIAS|F_QKVOUT><<<gQKV, 256, SMEM_GM5>>>(qa);

        vtrans_k<<<gVT, 256>>>(vh, vl, vth, vtl);
        flash_attn_k<<<gFA, 256, SMEM_FA>>>(qh, ql, kh, kl, vth, vtl, oh, ol);

        GemmArgs oa{};
        oa.Ahi = oh; oa.Alo = ol; oa.K = Dm; oa.ldc = Dm;
        oa.Bhi[0] = wc + OFF_O + oq; oa.Blo[0] = oa.Bhi[0] + (size_t)Dm*Dm;
        oa.bias[0] = bo + oDb; oa.Res = x; oa.C[0] = x;
        mma_gemm_k<F_BIAS|F_RES><<<gProj, 256, SMEM_GM>>>(oa);

        layernorm_split_k<<<TOK, 256>>>(x, ln2g + oDb, ln2b + oDb, hh, hl);

        GemmArgs fa{};
        fa.Ahi = hh; fa.Alo = hl; fa.K = Dm; fa.ldc = Ff;
        fa.Bhi[0] = wc + OFF_W1 + o1; fa.Blo[0] = fa.Bhi[0] + (size_t)Dm*Ff;
        fa.bias[0] = b1 + oFb; fa.Chi[0] = ffh; fa.Clo[0] = ffl;
        mma_gemm256_k<F_BIAS|F_RELU|F_SPLITOUT><<<gFfn1, 256, SMEM_GM5>>>(fa);

        GemmArgs f2{};
        f2.Ahi = ffh; f2.Alo = ffl; f2.K = Ff; f2.ldc = Dm;
        f2.Bhi[0] = wc + OFF_W2 + o1; f2.Blo[0] = f2.Bhi[0] + (size_t)Dm*Ff;
        f2.bias[0] = b2 + oDb; f2.Res = x; f2.C[0] = x;
        mma_gemm_k<F_BIAS|F_RES><<<gProj, 256, SMEM_GM>>>(f2);
    }

    layernorm_split_k<<<TOK, 256>>>(x, lnfg, lnfb, hh, hl);

    GemmArgs la{};
    la.Ahi = hh; la.Alo = hl; la.K = Dm; la.ldc = Vv;
    la.Bhi[0] = wc + OFF_WO; la.Blo[0] = la.Bhi[0] + (size_t)Dm*Vv;
    la.bias[0] = bout; la.C[0] = out;
    mma_gemm256_k<F_BIAS><<<gLogit, 256, SMEM_GM5>>>(la);
}

// round 16
// speedup vs baseline: 1.0867x; 1.0236x over previous
#include <cuda_runtime.h>
#include <cuda_bf16.h>
#include <cstdint>
#include <cstddef>

#define Bsz 2
#define Ssz 1024
#define Dm  1024
#define Hh  16
#define DKk 64
#define Ff  4096
#define Vv  32000
#define Ll  8
#define TOK (Bsz*Ssz)
#define BH  (Bsz*Hh)

// ===================== scratch ==============================================
__device__ float g_x [TOK*Dm];
__device__ __nv_bfloat16 g_hh[TOK*Dm],  g_hl[TOK*Dm];
__device__ __nv_bfloat16 g_oh[TOK*Dm],  g_ol[TOK*Dm];
__device__ __nv_bfloat16 g_ffh[TOK*Ff], g_ffl[TOK*Ff];
__device__ __nv_bfloat16 g_qh[TOK*Dm],  g_ql[TOK*Dm];    // [B,H,S,64]
__device__ __nv_bfloat16 g_kh[TOK*Dm],  g_kl[TOK*Dm];    // [B,H,S,64]
__device__ __nv_bfloat16 g_vh[TOK*Dm],  g_vl[TOK*Dm];    // [B,H,S,64]
__device__ __nv_bfloat16 g_vth[TOK*Dm], g_vtl[TOK*Dm];   // [B,H,64,S] transposed

#define SQW ((size_t)2*Dm*Dm)
#define SW1 ((size_t)2*Dm*Ff)
#define OFF_Q  ((size_t)0)
#define OFF_K  (OFF_Q  + (size_t)Ll*SQW)
#define OFF_V  (OFF_K  + (size_t)Ll*SQW)
#define OFF_O  (OFF_V  + (size_t)Ll*SQW)
#define OFF_W1 (OFF_O  + (size_t)Ll*SQW)
#define OFF_W2 (OFF_W1 + (size_t)Ll*SW1)
#define OFF_WO (OFF_W2 + (size_t)Ll*SW1)
#define WC_TOTAL (OFF_WO + (size_t)2*Dm*Vv)
__device__ __nv_bfloat16 g_wc[WC_TOTAL];

__device__ __forceinline__ void split_bf16(float v, __nv_bfloat16& h, __nv_bfloat16& l) {
    h = __float2bfloat16(v);
    l = __float2bfloat16(v - __bfloat162float(h));
}
__device__ __forceinline__ uint32_t pack2(__nv_bfloat16 a, __nv_bfloat16 b) {
    return (uint32_t)__bfloat16_as_ushort(a) | ((uint32_t)__bfloat16_as_ushort(b) << 16);
}
// fast exp on FMA pipe (x <= 0)
__device__ __forceinline__ float fexp(float x) {
    x = fmaxf(x, -80.0f);
    const float t = x * 1.4426950408889634f;
    const float f = floorf(t);
    const float r = t - f;
    float p = 1.53527593e-4f;
    p = fmaf(p, r, 1.33335581e-3f);
    p = fmaf(p, r, 9.61812911e-3f);
    p = fmaf(p, r, 5.55041087e-2f);
    p = fmaf(p, r, 2.40226507e-1f);
    p = fmaf(p, r, 6.93147182e-1f);
    p = fmaf(p, r, 1.0f);
    const float sc = __int_as_float(((int)f + 127) << 23);
    return p * sc;
}
__device__ __forceinline__ void cpa16(void* s, const void* g) {
    uint32_t sa = (uint32_t)__cvta_generic_to_shared(s);
    asm volatile("cp.async.cg.shared.global [%0], [%1], 16;" :: "r"(sa), "l"(g));
}
#define CP_COMMIT() asm volatile("cp.async.commit_group;" ::: "memory")
#define CP_WAIT1()  asm volatile("cp.async.wait_group 1;" ::: "memory")
#define CP_WAIT0()  asm volatile("cp.async.wait_group 0;" ::: "memory")

__device__ __forceinline__ void ldsm4(uint32_t addr, uint32_t* r) {
    asm volatile("ldmatrix.sync.aligned.m8n8.x4.shared.b16 {%0,%1,%2,%3}, [%4];"
        : "=r"(r[0]), "=r"(r[1]), "=r"(r[2]), "=r"(r[3]) : "r"(addr));
}
__device__ __forceinline__ void mma16816(float* d, const uint32_t* a, const uint32_t* b) {
    asm volatile("mma.sync.aligned.m16n8k16.row.col.f32.bf16.bf16.f32 "
        "{%0,%1,%2,%3}, {%4,%5,%6,%7}, {%8,%9}, {%0,%1,%2,%3};"
        : "+f"(d[0]), "+f"(d[1]), "+f"(d[2]), "+f"(d[3])
        : "r"(a[0]), "r"(a[1]), "r"(a[2]), "r"(a[3]), "r"(b[0]), "r"(b[1]));
}

// ======= weight convert: W [K,N] fp32 -> hi/lo [N,K] bf16 (transpose) =======
__global__ __launch_bounds__(256) void convert_w_k(
    const float* __restrict__ W, __nv_bfloat16* __restrict__ out, int Kd, int Nd)
{
    __shared__ float t[32][33];
    const int l = blockIdx.z;
    const float* Wl = W + (size_t)l * Kd * Nd;
    __nv_bfloat16* hi = out + (size_t)l * 2 * Kd * Nd;
    __nv_bfloat16* lo = hi + (size_t)Kd * Nd;
    const int nb = blockIdx.x * 32, kb = blockIdx.y * 32;
    const int tx = threadIdx.x & 31, ty = threadIdx.x >> 5;
    #pragma unroll
    for (int j = 0; j < 32; j += 8)
        t[ty + j][tx] = Wl[(size_t)(kb + ty + j) * Nd + nb + tx];
    __syncthreads();
    #pragma unroll
    for (int j = 0; j < 32; j += 8) {
        const int n = nb + ty + j, k = kb + tx;
        float v = t[tx][ty + j];
        __nv_bfloat16 h, l2; split_bf16(v, h, l2);
        hi[(size_t)n * Kd + k] = h;
        lo[(size_t)n * Kd + k] = l2;
    }
}

// ======= V transpose: [B,H,S,64] -> [B,H,64,S] ==============================
__global__ __launch_bounds__(256) void vtrans_k(
    const __nv_bfloat16* __restrict__ Vh, const __nv_bfloat16* __restrict__ Vl,
    __nv_bfloat16* __restrict__ Th, __nv_bfloat16* __restrict__ Tl)
{
    __shared__ __nv_bfloat16 th[64][68], tl[64][68];
    const int bh = blockIdx.y, s0 = blockIdx.x * 64;
    const int tid = threadIdx.x;
    const size_t ibase = ((size_t)bh * Ssz + s0) * DKk;
    #pragma unroll
    for (int ss = 0; ss < 4; ss++) {
        const int idx = tid + ss * 256;
        const int r = idx >> 4, c4 = (idx & 15) * 4;
        *(uint2*)&th[r][c4] = *(const uint2*)(Vh + ibase + (size_t)r * DKk + c4);
        *(uint2*)&tl[r][c4] = *(const uint2*)(Vl + ibase + (size_t)r * DKk + c4);
    }
    __syncthreads();
    const size_t obase = (size_t)bh * DKk * Ssz + s0;
    #pragma unroll
    for (int ss = 0; ss < 4; ss++) {
        const int idx = tid + ss * 256;
        const int dk = idx >> 4, s4 = (idx & 15) * 4;
        __nv_bfloat16 a[4], b[4];
        #pragma unroll
        for (int e = 0; e < 4; e++) { a[e] = th[s4 + e][dk]; b[e] = tl[s4 + e][dk]; }
        *(uint2*)(Th + obase + (size_t)dk * Ssz + s4) = *(uint2*)a;
        *(uint2*)(Tl + obase + (size_t)dk * Ssz + s4) = *(uint2*)b;
    }
}

// ===================== GEMM flags / args ====================================
#define F_BIAS 1
#define F_RES  2
#define F_RELU 4
#define F_QKVOUT 8
#define F_SPLITOUT 16

struct GemmArgs {
    const __nv_bfloat16 *Ahi, *Alo;
    const __nv_bfloat16 *Bhi[3], *Blo[3];
    const float* bias[3];
    const float* Res;
    float* C[3];
    __nv_bfloat16 *Chi[3], *Clo[3];
    int K;
    int ldc;
};

// ===================== GEMM v4: BM=128 ======================================
#define PITB 80
#define AH_OFF 0
#define AL_OFF (128*PITB)
#define BH_OFF (2*128*PITB)
#define BL_OFF (3*128*PITB)
#define STGB   (4*128*PITB)
#define SMEM_GM (3*STGB)               // 122880

template<int FLAGS>
__global__ __launch_bounds__(256) void mma_gemm_k(GemmArgs ga)
{
    constexpr int BM = 128, BN = 128, BK = 32;
    extern __shared__ __nv_bfloat16 smb[];
    char* smc = (char*)smb;

    const int tid = threadIdx.x, wid = tid >> 5, lane = tid & 31;
    const int z = blockIdx.z;
    const int Kd = ga.K;
    const __nv_bfloat16* Ah = ga.Ahi + (size_t)blockIdx.y * BM * Kd;
    const __nv_bfloat16* Al = ga.Alo + (size_t)blockIdx.y * BM * Kd;
    const __nv_bfloat16* Bh = ga.Bhi[z] + (size_t)blockIdx.x * BN * Kd;
    const __nv_bfloat16* Bl = ga.Blo[z] + (size_t)blockIdx.x * BN * Kd;
    const int wm = wid & 3, wn = wid >> 2;

    auto stage_load = [&](int buf, int k0) {
        char* s = smc + buf * STGB;
        #pragma unroll
        for (int ss = 0; ss < 2; ss++) {
            const int slot = tid + ss * 256;
            const int r = slot >> 2, c = slot & 3;
            cpa16(s + AH_OFF + r * PITB + c * 16, Ah + (size_t)r * Kd + k0 + c * 8);
            cpa16(s + AL_OFF + r * PITB + c * 16, Al + (size_t)r * Kd + k0 + c * 8);
        }
        #pragma unroll
        for (int ss = 0; ss < 2; ss++) {
            const int slot = tid + ss * 256;
            const int r = slot >> 2, c = slot & 3;
            cpa16(s + BH_OFF + r * PITB + c * 16, Bh + (size_t)r * Kd + k0 + c * 8);
            cpa16(s + BL_OFF + r * PITB + c * 16, Bl + (size_t)r * Kd + k0 + c * 8);
        }
        CP_COMMIT();
    };

    uint32_t offA[2];
    #pragma unroll
    for (int ii = 0; ii < 2; ii++)
        offA[ii] = (uint32_t)((wm * 32 + ii * 16 + (lane & 15)) * PITB + ((lane >> 4) & 1) * 16);
    uint32_t offB[4];
    #pragma unroll
    for (int jj = 0; jj < 4; jj++)
        offB[jj] = (uint32_t)((wn * 64 + jj * 16 + (lane & 7) + ((lane >> 4) & 1) * 8) * PITB
                              + ((lane >> 3) & 1) * 16);

    const uint32_t smem_u32 = (uint32_t)__cvta_generic_to_shared(smc);

    float acc[2][8][4];
    #pragma unroll
    for (int i = 0; i < 2; i++)
        #pragma unroll
        for (int j = 0; j < 8; j++)
            #pragma unroll
            for (int e = 0; e < 4; e++) acc[i][j][e] = 0.f;

    const int nst = Kd / BK;
    stage_load(0, 0);
    stage_load(1, BK);
    for (int i = 0; i < nst; i++) {
        if (i + 1 < nst) { CP_WAIT1(); } else { CP_WAIT0(); }
        __syncthreads();
        if (i + 2 < nst) stage_load((i + 2) % 3, (i + 2) * BK);
        const uint32_t sb = smem_u32 + (uint32_t)((i % 3) * STGB);
        #pragma unroll
        for (int kk = 0; kk < BK; kk += 16) {
            const uint32_t kb = sb + kk * 2;
            uint32_t ah[2][4], al[2][4], bh[16], bl[16];
            #pragma unroll
            for (int ii = 0; ii < 2; ii++) {
                ldsm4(kb + AH_OFF + offA[ii], ah[ii]);
                ldsm4(kb + AL_OFF + offA[ii], al[ii]);
            }
            #pragma unroll
            for (int jj = 0; jj < 4; jj++) {
                ldsm4(kb + BH_OFF + offB[jj], bh + jj * 4);
                ldsm4(kb + BL_OFF + offB[jj], bl + jj * 4);
            }
            #pragma unroll
            for (int ii = 0; ii < 2; ii++)
                #pragma unroll
                for (int j = 0; j < 8; j++) mma16816(acc[ii][j], ah[ii], bh + j * 2);
            #pragma unroll
            for (int ii = 0; ii < 2; ii++)
                #pragma unroll
                for (int j = 0; j < 8; j++) mma16816(acc[ii][j], ah[ii], bl + j * 2);
            #pragma unroll
            for (int ii = 0; ii < 2; ii++)
                #pragma unroll
                for (int j = 0; j < 8; j++) mma16816(acc[ii][j], al[ii], bh + j * 2);
        }
        __syncthreads();
    }

    constexpr int SP = BN + 4;
    float* st = (float*)smb;
    const int er = lane >> 2, ec = (lane & 3) * 2;
    #pragma unroll
    for (int ii = 0; ii < 2; ii++)
        #pragma unroll
        for (int j = 0; j < 8; j++) {
            const int r0 = wm * 32 + ii * 16 + er;
            const int c0 = wn * 64 + j * 8 + ec;
            st[r0 * SP + c0]       = acc[ii][j][0];
            st[r0 * SP + c0 + 1]   = acc[ii][j][1];
            st[(r0+8) * SP + c0]     = acc[ii][j][2];
            st[(r0+8) * SP + c0 + 1] = acc[ii][j][3];
        }
    __syncthreads();

    const float* bias = ga.bias[z] + (size_t)blockIdx.x * BN;
    #pragma unroll
    for (int jj = 0; jj < 16; jj++) {
        const int idx = tid + jj * 256;
        const int r = idx >> 5, c4 = (idx & 31) * 4;
        float4 v;
        v.x = st[r * SP + c4 + 0]; v.y = st[r * SP + c4 + 1];
        v.z = st[r * SP + c4 + 2]; v.w = st[r * SP + c4 + 3];
        if (FLAGS & F_BIAS) {
            float4 b4 = *(const float4*)(bias + c4);
            v.x += b4.x; v.y += b4.y; v.z += b4.z; v.w += b4.w;
        }
        if (FLAGS & F_RELU) {
            v.x = fmaxf(v.x, 0.f); v.y = fmaxf(v.y, 0.f);
            v.z = fmaxf(v.z, 0.f); v.w = fmaxf(v.w, 0.f);
        }
        if (FLAGS & F_QKVOUT) {
            const int token = blockIdx.y * BM + r;
            const int bb = token >> 10, ss = token & 1023;
            const int f = blockIdx.x * BN + c4;
            const int hh2 = f >> 6, dk = f & 63;
            const size_t base = (((size_t)bb * Hh + hh2) * Ssz + ss) * DKk + dk;
            __nv_bfloat16 h[4], l[4];
            split_bf16(v.x, h[0], l[0]); split_bf16(v.y, h[1], l[1]);
            split_bf16(v.z, h[2], l[2]); split_bf16(v.w, h[3], l[3]);
            *(uint2*)(ga.Chi[z] + base) = *(uint2*)h;
            *(uint2*)(ga.Clo[z] + base) = *(uint2*)l;
        } else if (FLAGS & F_SPLITOUT) {
            const size_t base = (size_t)(blockIdx.y * BM + r) * ga.ldc + blockIdx.x * BN + c4;
            __nv_bfloat16 h[4], l[4];
            split_bf16(v.x, h[0], l[0]); split_bf16(v.y, h[1], l[1]);
            split_bf16(v.z, h[2], l[2]); split_bf16(v.w, h[3], l[3]);
            *(uint2*)(ga.Chi[z] + base) = *(uint2*)h;
            *(uint2*)(ga.Clo[z] + base) = *(uint2*)l;
        } else {
            if (FLAGS & F_RES) {
                const float* R = ga.Res + (size_t)blockIdx.y * BM * ga.ldc + (size_t)blockIdx.x * BN;
                float4 r4 = *(const float4*)(R + (size_t)r * ga.ldc + c4);
                v.x += r4.x; v.y += r4.y; v.z += r4.z; v.w += r4.w;
            }
            float* C = ga.C[z] + (size_t)blockIdx.y * BM * ga.ldc + (size_t)blockIdx.x * BN;
            *(float4*)(C + (size_t)r * ga.ldc + c4) = v;
        }
    }
}

// ===================== GEMM v5: BM=256, warp tile 64x64, optional XY swap ===
#define AH5_OFF 0
#define AL5_OFF (256*PITB)
#define BH5_OFF (2*256*PITB)
#define BL5_OFF (2*256*PITB + 128*PITB)
#define STGB5   (2*256*PITB + 2*128*PITB)
#define SMEM_GM5 (3*STGB5)                   // 184320

template<int FLAGS, int SWAP>
__global__ __launch_bounds__(256) void mma_gemm256_k(GemmArgs ga)
{
    constexpr int BM = 256, BN = 128, BK = 32;
    extern __shared__ __nv_bfloat16 smb[];
    char* smc = (char*)smb;

    const int tid = threadIdx.x, wid = tid >> 5, lane = tid & 31;
    const int z = blockIdx.z;
    const int bnx = SWAP ? blockIdx.y : blockIdx.x;    // N tile index
    const int bmy = SWAP ? blockIdx.x : blockIdx.y;    // M tile index
    const int Kd = ga.K;
    const __nv_bfloat16* Ah = ga.Ahi + (size_t)bmy * BM * Kd;
    const __nv_bfloat16* Al = ga.Alo + (size_t)bmy * BM * Kd;
    const __nv_bfloat16* Bh = ga.Bhi[z] + (size_t)bnx * BN * Kd;
    const __nv_bfloat16* Bl = ga.Blo[z] + (size_t)bnx * BN * Kd;
    const int wm = wid & 3, wn = wid >> 2;

    auto stage_load = [&](int buf, int k0) {
        char* s = smc + buf * STGB5;
        #pragma unroll
        for (int ss = 0; ss < 4; ss++) {
            const int slot = tid + ss * 256;
            const int r = slot >> 2, c = slot & 3;
            cpa16(s + AH5_OFF + r * PITB + c * 16, Ah + (size_t)r * Kd + k0 + c * 8);
            cpa16(s + AL5_OFF + r * PITB + c * 16, Al + (size_t)r * Kd + k0 + c * 8);
        }
        #pragma unroll
        for (int ss = 0; ss < 2; ss++) {
            const int slot = tid + ss * 256;
            const int r = slot >> 2, c = slot & 3;
            cpa16(s + BH5_OFF + r * PITB + c * 16, Bh + (size_t)r * Kd + k0 + c * 8);
            cpa16(s + BL5_OFF + r * PITB + c * 16, Bl + (size_t)r * Kd + k0 + c * 8);
        }
        CP_COMMIT();
    };

    uint32_t offA[4];
    #pragma unroll
    for (int mi = 0; mi < 4; mi++)
        offA[mi] = (uint32_t)((wm * 64 + mi * 16 + (lane & 15)) * PITB + ((lane >> 4) & 1) * 16);
    uint32_t offB[4];
    #pragma unroll
    for (int nj = 0; nj < 4; nj++)
        offB[nj] = (uint32_t)((wn * 64 + nj * 16 + (lane & 7) + ((lane >> 4) & 1) * 8) * PITB
                              + ((lane >> 3) & 1) * 16);

    const uint32_t smem_u32 = (uint32_t)__cvta_generic_to_shared(smc);

    float acc[4][8][4];
    #pragma unroll
    for (int i = 0; i < 4; i++)
        #pragma unroll
        for (int j = 0; j < 8; j++)
            #pragma unroll
            for (int e = 0; e < 4; e++) acc[i][j][e] = 0.f;

    const int nst = Kd / BK;
    stage_load(0, 0);
    stage_load(1, BK);
    for (int i = 0; i < nst; i++) {
        if (i + 1 < nst) { CP_WAIT1(); } else { CP_WAIT0(); }
        __syncthreads();
        if (i + 2 < nst) stage_load((i + 2) % 3, (i + 2) * BK);
        const uint32_t sb = smem_u32 + (uint32_t)((i % 3) * STGB5);
        #pragma unroll
        for (int kk = 0; kk < BK; kk += 16) {
            const uint32_t kb = sb + kk * 2;
            uint32_t ah[4][4], al[4][4], bb[16];
            #pragma unroll
            for (int mi = 0; mi < 4; mi++) {
                ldsm4(kb + AH5_OFF + offA[mi], ah[mi]);
                ldsm4(kb + AL5_OFF + offA[mi], al[mi]);
            }
            #pragma unroll
            for (int nj = 0; nj < 4; nj++) ldsm4(kb + BH5_OFF + offB[nj], bb + nj * 4);
            #pragma unroll
            for (int mi = 0; mi < 4; mi++)
                #pragma unroll
                for (int j = 0; j < 8; j++) mma16816(acc[mi][j], ah[mi], bb + j * 2);
            #pragma unroll
            for (int mi = 0; mi < 4; mi++)
                #pragma unroll
                for (int j = 0; j < 8; j++) mma16816(acc[mi][j], al[mi], bb + j * 2);
            #pragma unroll
            for (int nj = 0; nj < 4; nj++) ldsm4(kb + BL5_OFF + offB[nj], bb + nj * 4);
            #pragma unroll
            for (int mi = 0; mi < 4; mi++)
                #pragma unroll
                for (int j = 0; j < 8; j++) mma16816(acc[mi][j], ah[mi], bb + j * 2);
        }
        __syncthreads();
    }

    constexpr int SP = BN + 4;
    float* st = (float*)smb;
    const int er = lane >> 2, ec = (lane & 3) * 2;
    #pragma unroll
    for (int mi = 0; mi < 4; mi++)
        #pragma unroll
        for (int j = 0; j < 8; j++) {
            const int r0 = wm * 64 + mi * 16 + er;
            const int c0 = wn * 64 + j * 8 + ec;
            st[r0 * SP + c0]       = acc[mi][j][0];
            st[r0 * SP + c0 + 1]   = acc[mi][j][1];
            st[(r0+8) * SP + c0]     = acc[mi][j][2];
            st[(r0+8) * SP + c0 + 1] = acc[mi][j][3];
        }
    __syncthreads();

    const float* bias = ga.bias[z] + (size_t)bnx * BN;
    #pragma unroll
    for (int jj = 0; jj < 32; jj++) {
        const int idx = tid + jj * 256;
        const int r = idx >> 5, c4 = (idx & 31) * 4;
        float4 v;
        v.x = st[r * SP + c4 + 0]; v.y = st[r * SP + c4 + 1];
        v.z = st[r * SP + c4 + 2]; v.w = st[r * SP + c4 + 3];
        if (FLAGS & F_BIAS) {
            float4 b4 = *(const float4*)(bias + c4);
            v.x += b4.x; v.y += b4.y; v.z += b4.z; v.w += b4.w;
        }
        if (FLAGS & F_RELU) {
            v.x = fmaxf(v.x, 0.f); v.y = fmaxf(v.y, 0.f);
            v.z = fmaxf(v.z, 0.f); v.w = fmaxf(v.w, 0.f);
        }
        if (FLAGS & F_QKVOUT) {
            const int token = bmy * BM + r;
            const int bb2 = token >> 10, ss = token & 1023;
            const int f = bnx * BN + c4;
            const int hh2 = f >> 6, dk = f & 63;
            const size_t base = (((size_t)bb2 * Hh + hh2) * Ssz + ss) * DKk + dk;
            __nv_bfloat16 h[4], l[4];
            split_bf16(v.x, h[0], l[0]); split_bf16(v.y, h[1], l[1]);
            split_bf16(v.z, h[2], l[2]); split_bf16(v.w, h[3], l[3]);
            *(uint2*)(ga.Chi[z] + base) = *(uint2*)h;
            *(uint2*)(ga.Clo[z] + base) = *(uint2*)l;
        } else if (FLAGS & F_SPLITOUT) {
            const size_t base = (size_t)(bmy * BM + r) * ga.ldc + bnx * BN + c4;
            __nv_bfloat16 h[4], l[4];
            split_bf16(v.x, h[0], l[0]); split_bf16(v.y, h[1], l[1]);
            split_bf16(v.z, h[2], l[2]); split_bf16(v.w, h[3], l[3]);
            *(uint2*)(ga.Chi[z] + base) = *(uint2*)h;
            *(uint2*)(ga.Clo[z] + base) = *(uint2*)l;
        } else {
            if (FLAGS & F_RES) {
                const float* R = ga.Res + (size_t)bmy * BM * ga.ldc + (size_t)bnx * BN;
                float4 r4 = *(const float4*)(R + (size_t)r * ga.ldc + c4);
                v.x += r4.x; v.y += r4.y; v.z += r4.z; v.w += r4.w;
            }
            float* C = ga.C[z] + (size_t)bmy * BM * ga.ldc + (size_t)bnx * BN;
            *(float4*)(C + (size_t)r * ga.ldc + c4) = v;
        }
    }
}

// ===================== fused causal flash attention =========================
#define QPIT 72
#define VPIT 136
#define SQH_E 0
#define SQL_E (128*QPIT)
#define SKH_E (2*128*QPIT)
#define SKL_E (3*128*QPIT)
#define SVH_E (4*128*QPIT)
#define SVL_E (4*128*QPIT + 64*VPIT)
#define SMEM_FA ((4*128*QPIT + 2*64*VPIT) * 2)   // 108544 bytes

__global__ __launch_bounds__(256) void flash_attn_k(
    const __nv_bfloat16* __restrict__ Qh, const __nv_bfloat16* __restrict__ Ql,
    const __nv_bfloat16* __restrict__ Kh, const __nv_bfloat16* __restrict__ Kl,
    const __nv_bfloat16* __restrict__ Vth, const __nv_bfloat16* __restrict__ Vtl,
    __nv_bfloat16* __restrict__ Oh, __nv_bfloat16* __restrict__ Ol)
{
    const int bm = 7 - blockIdx.x;
    const int bh = blockIdx.y, bb = bh >> 4, hh = bh & 15;
    extern __shared__ __nv_bfloat16 sm[];
    const int tid = threadIdx.x, wid = tid >> 5, lane = tid & 31;

    const size_t qoff = ((size_t)bh * Ssz + bm * 128) * DKk;
    #pragma unroll
    for (int s = 0; s < 4; s++) {
        const int slot = tid + s * 256;
        const int r = slot >> 3, c8 = slot & 7;
        *(uint4*)&sm[SQH_E + r * QPIT + c8 * 8] = *(const uint4*)(Qh + qoff + (size_t)r * DKk + c8 * 8);
        *(uint4*)&sm[SQL_E + r * QPIT + c8 * 8] = *(const uint4*)(Ql + qoff + (size_t)r * DKk + c8 * 8);
    }

    const uint32_t smem_b = (uint32_t)__cvta_generic_to_shared(sm);
    const uint32_t offQ = (uint32_t)((wid * 16 + (lane & 15)) * QPIT * 2 + ((lane >> 4) & 1) * 16);
    uint32_t offK[8];
    #pragma unroll
    for (int nj = 0; nj < 8; nj++)
        offK[nj] = (uint32_t)((nj * 16 + (lane & 7) + ((lane >> 4) & 1) * 8) * QPIT * 2
                              + ((lane >> 3) & 1) * 16);
    uint32_t offV[4];
    #pragma unroll
    for (int nj = 0; nj < 4; nj++)
        offV[nj] = (uint32_t)((nj * 16 + (lane & 7) + ((lane >> 4) & 1) * 8) * VPIT * 2
                              + ((lane >> 3) & 1) * 16);

    float accO[8][4];
    #pragma unroll
    for (int n = 0; n < 8; n++)
        #pragma unroll
        for (int e = 0; e < 4; e++) accO[n][e] = 0.f;
    float m0 = -3.0e38f, m1 = -3.0e38f, s0 = 0.f, s1 = 0.f;

    const int r_in = lane >> 2;
    const int row_g0 = bm * 128 + wid * 16 + r_in;
    const int cb = 2 * (lane & 3);

    for (int bn = 0; bn <= bm; bn++) {
        const size_t koff = ((size_t)bh * Ssz + bn * 128) * DKk;
        #pragma unroll
        for (int s = 0; s < 4; s++) {
            const int slot = tid + s * 256;
            const int r = slot >> 3, c8 = slot & 7;
            *(uint4*)&sm[SKH_E + r * QPIT + c8 * 8] = *(const uint4*)(Kh + koff + (size_t)r * DKk + c8 * 8);
            *(uint4*)&sm[SKL_E + r * QPIT + c8 * 8] = *(const uint4*)(Kl + koff + (size_t)r * DKk + c8 * 8);
        }
        const size_t voff = (size_t)bh * DKk * Ssz + bn * 128;
        #pragma unroll
        for (int s = 0; s < 4; s++) {
            const int slot = tid + s * 256;
            const int r = slot >> 4, c = slot & 15;
            *(uint4*)&sm[SVH_E + r * VPIT + c * 8] = *(const uint4*)(Vth + voff + (size_t)r * Ssz + c * 8);
            *(uint4*)&sm[SVL_E + r * VPIT + c * 8] = *(const uint4*)(Vtl + voff + (size_t)r * Ssz + c * 8);
        }
        __syncthreads();

        float sacc[16][4];
        #pragma unroll
        for (int j = 0; j < 16; j++)
            #pragma unroll
            for (int e = 0; e < 4; e++) sacc[j][e] = 0.f;
        #pragma unroll
        for (int kk = 0; kk < 4; kk++) {
            uint32_t q4[4], ql4[4], kb4[4];
            ldsm4(smem_b + SQH_E * 2 + offQ + kk * 32, q4);
            ldsm4(smem_b + SQL_E * 2 + offQ + kk * 32, ql4);
            #pragma unroll
            for (int nj = 0; nj < 8; nj++) {
                ldsm4(smem_b + SKH_E * 2 + offK[nj] + kk * 32, kb4);
                mma16816(sacc[2*nj],   q4,  kb4);
                mma16816(sacc[2*nj+1], q4,  kb4 + 2);
                mma16816(sacc[2*nj],   ql4, kb4);
                mma16816(sacc[2*nj+1], ql4, kb4 + 2);
                ldsm4(smem_b + SKL_E * 2 + offK[nj] + kk * 32, kb4);
                mma16816(sacc[2*nj],   q4,  kb4);
                mma16816(sacc[2*nj+1], q4,  kb4 + 2);
            }
        }

        const float scale = 0.125f;
        if (bn == bm) {
            #pragma unroll
            for (int j = 0; j < 16; j++)
                #pragma unroll
                for (int e = 0; e < 4; e++) {
                    const int col = bn * 128 + j * 8 + cb + (e & 1);
                    const int row = row_g0 + ((e >= 2) ? 8 : 0);
                    sacc[j][e] = (col <= row) ? sacc[j][e] * scale : -3.0e38f;
                }
        } else {
            #pragma unroll
            for (int j = 0; j < 16; j++)
                #pragma unroll
                for (int e = 0; e < 4; e++) sacc[j][e] *= scale;
        }

        float tm0 = -3.0e38f, tm1 = -3.0e38f;
        #pragma unroll
        for (int j = 0; j < 16; j++) {
            tm0 = fmaxf(tm0, fmaxf(sacc[j][0], sacc[j][1]));
            tm1 = fmaxf(tm1, fmaxf(sacc[j][2], sacc[j][3]));
        }
        tm0 = fmaxf(tm0, __shfl_xor_sync(0xffffffffu, tm0, 1));
        tm0 = fmaxf(tm0, __shfl_xor_sync(0xffffffffu, tm0, 2));
        tm1 = fmaxf(tm1, __shfl_xor_sync(0xffffffffu, tm1, 1));
        tm1 = fmaxf(tm1, __shfl_xor_sync(0xffffffffu, tm1, 2));
        const float nm0 = fmaxf(m0, tm0), nm1 = fmaxf(m1, tm1);
        const float a0 = fexp(m0 - nm0), a1 = fexp(m1 - nm1);
        m0 = nm0; m1 = nm1;
        float ps0 = 0.f, ps1 = 0.f;
        #pragma unroll
        for (int j = 0; j < 16; j++) {
            sacc[j][0] = fexp(sacc[j][0] - m0); ps0 += sacc[j][0];
            sacc[j][1] = fexp(sacc[j][1] - m0); ps0 += sacc[j][1];
            sacc[j][2] = fexp(sacc[j][2] - m1); ps1 += sacc[j][2];
            sacc[j][3] = fexp(sacc[j][3] - m1); ps1 += sacc[j][3];
        }
        s0 = s0 * a0 + ps0;
        s1 = s1 * a1 + ps1;
        #pragma unroll
        for (int n = 0; n < 8; n++) {
            accO[n][0] *= a0; accO[n][1] *= a0;
            accO[n][2] *= a1; accO[n][3] *= a1;
        }

        #pragma unroll
        for (int t = 0; t < 8; t++) {
            uint32_t ph4[4], pl4[4];
            {
                __nv_bfloat16 h0, l0, h1, l1;
                split_bf16(sacc[2*t][0], h0, l0);   split_bf16(sacc[2*t][1], h1, l1);
                ph4[0] = pack2(h0, h1); pl4[0] = pack2(l0, l1);
                split_bf16(sacc[2*t][2], h0, l0);   split_bf16(sacc[2*t][3], h1, l1);
                ph4[1] = pack2(h0, h1); pl4[1] = pack2(l0, l1);
                split_bf16(sacc[2*t+1][0], h0, l0); split_bf16(sacc[2*t+1][1], h1, l1);
                ph4[2] = pack2(h0, h1); pl4[2] = pack2(l0, l1);
                split_bf16(sacc[2*t+1][2], h0, l0); split_bf16(sacc[2*t+1][3], h1, l1);
                ph4[3] = pack2(h0, h1); pl4[3] = pack2(l0, l1);
            }
            #pragma unroll
            for (int nj = 0; nj < 4; nj++) {
                uint32_t vb[4];
                ldsm4(smem_b + SVH_E * 2 + offV[nj] + t * 32, vb);
                mma16816(accO[2*nj],   ph4, vb);
                mma16816(accO[2*nj+1], ph4, vb + 2);
                mma16816(accO[2*nj],   pl4, vb);
                mma16816(accO[2*nj+1], pl4, vb + 2);
                ldsm4(smem_b + SVL_E * 2 + offV[nj] + t * 32, vb);
                mma16816(accO[2*nj],   ph4, vb);
                mma16816(accO[2*nj+1], ph4, vb + 2);
            }
        }
        __syncthreads();
    }

    s0 += __shfl_xor_sync(0xffffffffu, s0, 1);
    s0 += __shfl_xor_sync(0xffffffffu, s0, 2);
    s1 += __shfl_xor_sync(0xffffffffu, s1, 1);
    s1 += __shfl_xor_sync(0xffffffffu, s1, 2);
    const float i0 = 1.0f / s0, i1 = 1.0f / s1;
    #pragma unroll
    for (int n = 0; n < 8; n++)
        #pragma unroll
        for (int e = 0; e < 4; e++) {
            const int row = row_g0 + ((e >= 2) ? 8 : 0);
            const int col = n * 8 + cb + (e & 1);
            const float o = accO[n][e] * ((e < 2) ? i0 : i1);
            __nv_bfloat16 h, l; split_bf16(o, h, l);
            const size_t base = ((size_t)bb * Ssz + row) * Dm + hh * DKk + col;
            Oh[base] = h; Ol[base] = l;
        }
}

// ===================== embedding / layernorm (split out) ====================
__global__ __launch_bounds__(256) void embed_k(
    const int* __restrict__ ids, const float* __restrict__ tok,
    const float* __restrict__ pos, float* __restrict__ x)
{
    const int row = blockIdx.x;
    const int s   = row & (Ssz - 1);
    const int id  = ids[row];
    const int t   = threadIdx.x;
    float4 tv = *(const float4*)(tok + (size_t)id * Dm + t * 4);
    float4 pv = *(const float4*)(pos + (size_t)s  * Dm + t * 4);
    float4 o; o.x = tv.x + pv.x; o.y = tv.y + pv.y; o.z = tv.z + pv.z; o.w = tv.w + pv.w;
    *(float4*)(x + (size_t)row * Dm + t * 4) = o;
}

__global__ __launch_bounds__(256) void layernorm_split_k(
    const float* __restrict__ x, const float* __restrict__ g,
    const float* __restrict__ be,
    __nv_bfloat16* __restrict__ oh, __nv_bfloat16* __restrict__ ol)
{
    const int row = blockIdx.x;
    const int t   = threadIdx.x;
    const float* xr = x + (size_t)row * Dm;
    float4 v = *(const float4*)(xr + t * 4);
    float s  = v.x + v.y + v.z + v.w;
    float ss = v.x*v.x + v.y*v.y + v.z*v.z + v.w*v.w;
    #pragma unroll
    for (int off = 16; off; off >>= 1) {
        s  += __shfl_xor_sync(0xffffffffu, s,  off);
        ss += __shfl_xor_sync(0xffffffffu, ss, off);
    }
    __shared__ float rs[8], rss[8];
    const int warp = t >> 5, lane = t & 31;
    if (lane == 0) { rs[warp] = s; rss[warp] = ss; }
    __syncthreads();
    s = 0.f; ss = 0.f;
    #pragma unroll
    for (int i = 0; i < 8; i++) { s += rs[i]; ss += rss[i]; }
    const float mean = s  * (1.0f / Dm);
    const float var  = ss * (1.0f / Dm) - mean * mean;
    const float rstd = rsqrtf(var + 1e-5f);
    float4 gv = *(const float4*)(g  + t * 4);
    float4 bv = *(const float4*)(be + t * 4);
    float o0 = (v.x - mean) * rstd * gv.x + bv.x;
    float o1 = (v.y - mean) * rstd * gv.y + bv.y;
    float o2 = (v.z - mean) * rstd * gv.z + bv.z;
    float o3 = (v.w - mean) * rstd * gv.w + bv.w;
    __nv_bfloat16 h[4], l[4];
    split_bf16(o0, h[0], l[0]); split_bf16(o1, h[1], l[1]);
    split_bf16(o2, h[2], l[2]); split_bf16(o3, h[3], l[3]);
    *(uint2*)(oh + (size_t)row * Dm + t * 4) = *(uint2*)h;
    *(uint2*)(ol + (size_t)row * Dm + t * 4) = *(uint2*)l;
}

// ===================== driver ===============================================
extern "C" void kernel_launch(void* const* d_in, const int* in_sizes, int n_in,
                              void* d_out, int out_size)
{
    const int*   ids  = (const int*)  d_in[0];
    const float* tok  = (const float*)d_in[1];
    const float* pos  = (const float*)d_in[2];
    const float* Wq   = (const float*)d_in[3];
    const float* bq   = (const float*)d_in[4];
    const float* Wk   = (const float*)d_in[5];
    const float* bk   = (const float*)d_in[6];
    const float* Wv   = (const float*)d_in[7];
    const float* bv   = (const float*)d_in[8];
    const float* Wo   = (const float*)d_in[9];
    const float* bo   = (const float*)d_in[10];
    const float* W1   = (const float*)d_in[11];
    const float* b1   = (const float*)d_in[12];
    const float* W2   = (const float*)d_in[13];
    const float* b2   = (const float*)d_in[14];
    const float* ln1g = (const float*)d_in[15];
    const float* ln1b = (const float*)d_in[16];
    const float* ln2g = (const float*)d_in[17];
    const float* ln2b = (const float*)d_in[18];
    const float* lnfg = (const float*)d_in[19];
    const float* lnfb = (const float*)d_in[20];
    const float* Wout = (const float*)d_in[21];
    const float* bout = (const float*)d_in[22];
    float* out = (float*)d_out;

    float *x;
    __nv_bfloat16 *wc, *hh, *hl, *oh, *ol, *ffh, *ffl;
    __nv_bfloat16 *qh, *ql, *kh, *kl, *vh, *vl, *vth, *vtl;
    cudaGetSymbolAddress((void**)&x,  g_x);
    cudaGetSymbolAddress((void**)&wc, g_wc);
    cudaGetSymbolAddress((void**)&hh, g_hh);   cudaGetSymbolAddress((void**)&hl, g_hl);
    cudaGetSymbolAddress((void**)&oh, g_oh);   cudaGetSymbolAddress((void**)&ol, g_ol);
    cudaGetSymbolAddress((void**)&ffh, g_ffh); cudaGetSymbolAddress((void**)&ffl, g_ffl);
    cudaGetSymbolAddress((void**)&qh, g_qh);   cudaGetSymbolAddress((void**)&ql, g_ql);
    cudaGetSymbolAddress((void**)&kh, g_kh);   cudaGetSymbolAddress((void**)&kl, g_kl);
    cudaGetSymbolAddress((void**)&vh, g_vh);   cudaGetSymbolAddress((void**)&vl, g_vl);
    cudaGetSymbolAddress((void**)&vth, g_vth); cudaGetSymbolAddress((void**)&vtl, g_vtl);

    cudaFuncSetAttribute(mma_gemm_k<F_BIAS|F_RES>,    cudaFuncAttributeMaxDynamicSharedMemorySize, SMEM_GM);
    cudaFuncSetAttribute(mma_gemm_k<F_BIAS|F_QKVOUT>, cudaFuncAttributeMaxDynamicSharedMemorySize, SMEM_GM);
    cudaFuncSetAttribute(mma_gemm256_k<F_BIAS, 1>,                     cudaFuncAttributeMaxDynamicSharedMemorySize, SMEM_GM5);
    cudaFuncSetAttribute(mma_gemm256_k<F_BIAS|F_RELU|F_SPLITOUT, 0>,   cudaFuncAttributeMaxDynamicSharedMemorySize, SMEM_GM5);
    cudaFuncSetAttribute(flash_attn_k, cudaFuncAttributeMaxDynamicSharedMemorySize, SMEM_FA);

    convert_w_k<<<dim3(Dm/32, Dm/32, Ll), 256>>>(Wq,   wc + OFF_Q,  Dm, Dm);
    convert_w_k<<<dim3(Dm/32, Dm/32, Ll), 256>>>(Wk,   wc + OFF_K,  Dm, Dm);
    convert_w_k<<<dim3(Dm/32, Dm/32, Ll), 256>>>(Wv,   wc + OFF_V,  Dm, Dm);
    convert_w_k<<<dim3(Dm/32, Dm/32, Ll), 256>>>(Wo,   wc + OFF_O,  Dm, Dm);
    convert_w_k<<<dim3(Ff/32, Dm/32, Ll), 256>>>(W1,   wc + OFF_W1, Dm, Ff);
    convert_w_k<<<dim3(Dm/32, Ff/32, Ll), 256>>>(W2,   wc + OFF_W2, Ff, Dm);
    convert_w_k<<<dim3(Vv/32, Dm/32, 1),  256>>>(Wout, wc + OFF_WO, Dm, Vv);

    embed_k<<<TOK, 256>>>(ids, tok, pos, x);

    const dim3 gQKV (Dm/128, TOK/128, 3);      // v4: 384 CTAs, tail 13.5%
    const dim3 gProj(Dm/128, TOK/128, 1);      // v4: 128 CTAs
    const dim3 gFfn1(Ff/128, TOK/256, 1);      // v5: 256 CTAs
    const dim3 gLogit(TOK/256, Vv/128, 1);     // v5 SWAP: M-major waves, B stays in L2
    const dim3 gFA(Ssz/128, BH, 1);
    const dim3 gVT(Ssz/64, BH, 1);

    for (int l = 0; l < Ll; l++) {
        const size_t oDb = (size_t)l * Dm;
        const size_t oFb = (size_t)l * Ff;
        const size_t oq = (size_t)l * SQW, o1 = (size_t)l * SW1;

        layernorm_split_k<<<TOK, 256>>>(x, ln1g + oDb, ln1b + oDb, hh, hl);

        GemmArgs qa{};
        qa.Ahi = hh; qa.Alo = hl; qa.K = Dm; qa.ldc = Dm;
        qa.Bhi[0] = wc + OFF_Q + oq; qa.Blo[0] = qa.Bhi[0] + (size_t)Dm*Dm;
        qa.Bhi[1] = wc + OFF_K + oq; qa.Blo[1] = qa.Bhi[1] + (size_t)Dm*Dm;
        qa.Bhi[2] = wc + OFF_V + oq; qa.Blo[2] = qa.Bhi[2] + (size_t)Dm*Dm;
        qa.bias[0] = bq + oDb; qa.bias[1] = bk + oDb; qa.bias[2] = bv + oDb;
        qa.Chi[0] = qh; qa.Clo[0] = ql;
        qa.Chi[1] = kh; qa.Clo[1] = kl;
        qa.Chi[2] = vh; qa.Clo[2] = vl;
        mma_gemm_k<F_BIAS|F_QKVOUT><<<gQKV, 256, SMEM_GM>>>(qa);

        vtrans_k<<<gVT, 256>>>(vh, vl, vth, vtl);
        flash_attn_k<<<gFA, 256, SMEM_FA>>>(qh, ql, kh, kl, vth, vtl, oh, ol);

        GemmArgs oa{};
        oa.Ahi = oh; oa.Alo = ol; oa.K = Dm; oa.ldc = Dm;
        oa.Bhi[0] = wc + OFF_O + oq; oa.Blo[0] = oa.Bhi[0] + (size_t)Dm*Dm;
        oa.bias[0] = bo + oDb; oa.Res = x; oa.C[0] = x;
        mma_gemm_k<F_BIAS|F_RES><<<gProj, 256, SMEM_GM>>>(oa);

        layernorm_split_k<<<TOK, 256>>>(x, ln2g + oDb, ln2b + oDb, hh, hl);

        GemmArgs fa{};
        fa.Ahi = hh; fa.Alo = hl; fa.K = Dm; fa.ldc = Ff;
        fa.Bhi[0] = wc + OFF_W1 + o1; fa.Blo[0] = fa.Bhi[0] + (size_t)Dm*Ff;
        fa.bias[0] = b1 + oFb; fa.Chi[0] = ffh; fa.Clo[0] = ffl;
        mma_gemm256_k<F_BIAS|F_RELU|F_SPLITOUT, 0><<<gFfn1, 256, SMEM_GM5>>>(fa);

        GemmArgs f2{};
        f2.Ahi = ffh; f2.Alo = ffl; f2.K = Ff; f2.ldc = Dm;
        f2.Bhi[0] = wc + OFF_W2 + o1; f2.Blo[0] = f2.Bhi[0] + (size_t)Dm*Ff;
        f2.bias[0] = b2 + oDb; f2.Res = x; f2.C[0] = x;
        mma_gemm_k<F_BIAS|F_RES><<<gProj, 256, SMEM_GM>>>(f2);
    }

    layernorm_split_k<<<TOK, 256>>>(x, lnfg, lnfb, hh, hl);

    GemmArgs la{};
    la.Ahi = hh; la.Alo = hl; la.K = Dm; la.ldc = Vv;
    la.Bhi[0] = wc + OFF_WO; la.Blo[0] = la.Bhi[0] + (size_t)Dm*Vv;
    la.bias[0] = bout; la.C[0] = out;
    mma_gemm256_k<F_BIAS, 1><<<gLogit, 256, SMEM_GM5>>>(la);
}